// round 1
// baseline (speedup 1.0000x reference)
#include <cuda_runtime.h>
#include <cstddef>

// Problem constants
#define BB 2
#define SS 2048
#define DD 1024
#define HH 16
#define HDD 64
#define DM 256  // D/4

// Scratch (device globals — no runtime allocation allowed)
__device__ float g_q[BB*HH*SS*HDD];
__device__ float g_k[BB*HH*SS*HDD];
__device__ float g_v[BB*HH*SS*HDD];
__device__ float g_attn[BB*HH*SS*HDD];
__device__ float g_hid[BB*SS*DM];
__device__ float g_mod[BB*SS*DD];
__device__ float g_x[BB*SS*DD];

// ---------------------------------------------------------------------------
// Generic NT GEMM: C[M,N] = A[M,K] @ W[N,K]^T + bias[N]
// 64x64 tile, BK=16, 256 threads, 4x4 microtile per thread.
// split_out=1 writes C in [B,H,S,HD] head-split layout (fused transpose).
// relu=1 applies ReLU.
// ---------------------------------------------------------------------------
__global__ void gemm_nt_kernel(const float* __restrict__ A,
                               const float* __restrict__ W,
                               const float* __restrict__ bias,
                               float* __restrict__ C,
                               int M, int N, int K,
                               int relu, int split_out)
{
    __shared__ float As[64][17];
    __shared__ float Ws[64][17];

    const int tid = threadIdx.x;
    const int tx = tid & 15;
    const int ty = tid >> 4;
    const int m0 = blockIdx.y << 6;
    const int n0 = blockIdx.x << 6;
    const int lr = tid >> 2;            // 0..63 (row within tile for loads)
    const int lc = (tid & 3) << 2;      // 0,4,8,12 (col within BK for loads)

    float acc[4][4];
    #pragma unroll
    for (int i = 0; i < 4; i++)
        #pragma unroll
        for (int j = 0; j < 4; j++) acc[i][j] = 0.f;

    const float* Ap = A + (size_t)(m0 + lr) * K + lc;
    const float* Wp = W + (size_t)(n0 + lr) * K + lc;

    for (int k0 = 0; k0 < K; k0 += 16) {
        float4 av = *(const float4*)(Ap + k0);
        float4 wv = *(const float4*)(Wp + k0);
        As[lr][lc+0] = av.x; As[lr][lc+1] = av.y; As[lr][lc+2] = av.z; As[lr][lc+3] = av.w;
        Ws[lr][lc+0] = wv.x; Ws[lr][lc+1] = wv.y; Ws[lr][lc+2] = wv.z; Ws[lr][lc+3] = wv.w;
        __syncthreads();

        #pragma unroll
        for (int kk = 0; kk < 16; kk++) {
            float a[4], b[4];
            #pragma unroll
            for (int i = 0; i < 4; i++) a[i] = As[ty*4+i][kk];
            #pragma unroll
            for (int j = 0; j < 4; j++) b[j] = Ws[tx*4+j][kk];
            #pragma unroll
            for (int i = 0; i < 4; i++)
                #pragma unroll
                for (int j = 0; j < 4; j++)
                    acc[i][j] = fmaf(a[i], b[j], acc[i][j]);
        }
        __syncthreads();
    }

    #pragma unroll
    for (int i = 0; i < 4; i++) {
        const int m = m0 + ty*4 + i;
        #pragma unroll
        for (int j = 0; j < 4; j++) {
            const int n = n0 + tx*4 + j;
            float v = acc[i][j] + bias[n];
            if (relu) v = fmaxf(v, 0.f);
            if (split_out) {
                const int b = m / SS, s = m % SS;
                const int h = n >> 6, hd = n & 63;
                C[(((size_t)(b*HH + h))*SS + s)*HDD + hd] = v;
            } else {
                C[(size_t)m * N + n] = v;
            }
        }
    }
}

// ---------------------------------------------------------------------------
// Flash attention: per (b,h), 64 query rows per CTA, online softmax over
// 32 key tiles of 64, P@V accumulated in registers. HD=64 resident in smem.
// Q is pre-scaled by HD^-0.5 at load.
// ---------------------------------------------------------------------------
__global__ void attn_kernel()
{
    const int bh = blockIdx.y;                 // 0..B*H-1
    const int m0 = blockIdx.x << 6;            // query tile base
    const float* Qg = g_q + (size_t)bh * SS * HDD;
    const float* Kg = g_k + (size_t)bh * SS * HDD;
    const float* Vg = g_v + (size_t)bh * SS * HDD;
    float*       Og = g_attn + (size_t)bh * SS * HDD;

    __shared__ float Qs[64][HDD + 1];
    __shared__ float Ks[64][HDD + 1];   // reused for V
    __shared__ float Ps[64][65];

    const int tid = threadIdx.x;
    const int tx = tid & 15;
    const int ty = tid >> 4;
    const int lr = tid >> 2;            // 0..63
    const int lc = (tid & 3) << 4;      // 0,16,32,48 (16 floats per thread)

    const float scale = 0.125f;         // HD^-0.5

    // Load Q tile, pre-scaled
    {
        const float* src = Qg + (size_t)(m0 + lr) * HDD + lc;
        #pragma unroll
        for (int u = 0; u < 4; u++) {
            float4 v4 = *(const float4*)(src + u*4);
            Qs[lr][lc + u*4 + 0] = v4.x * scale;
            Qs[lr][lc + u*4 + 1] = v4.y * scale;
            Qs[lr][lc + u*4 + 2] = v4.z * scale;
            Qs[lr][lc + u*4 + 3] = v4.w * scale;
        }
    }

    float m_i[4], l_i[4], o[4][4];
    #pragma unroll
    for (int i = 0; i < 4; i++) {
        m_i[i] = -1e30f; l_i[i] = 0.f;
        #pragma unroll
        for (int j = 0; j < 4; j++) o[i][j] = 0.f;
    }

    for (int kt = 0; kt < SS/64; kt++) {
        const int kbase = kt << 6;

        // Load K tile
        {
            const float* src = Kg + (size_t)(kbase + lr) * HDD + lc;
            #pragma unroll
            for (int u = 0; u < 4; u++) {
                float4 v4 = *(const float4*)(src + u*4);
                Ks[lr][lc + u*4 + 0] = v4.x;
                Ks[lr][lc + u*4 + 1] = v4.y;
                Ks[lr][lc + u*4 + 2] = v4.z;
                Ks[lr][lc + u*4 + 3] = v4.w;
            }
        }
        __syncthreads();

        // S = Qs @ Ks^T  (64x64, 4x4 per thread)
        float sreg[4][4];
        #pragma unroll
        for (int i = 0; i < 4; i++)
            #pragma unroll
            for (int j = 0; j < 4; j++) sreg[i][j] = 0.f;
        #pragma unroll 8
        for (int kk = 0; kk < HDD; kk++) {
            float a[4], b[4];
            #pragma unroll
            for (int i = 0; i < 4; i++) a[i] = Qs[ty*4+i][kk];
            #pragma unroll
            for (int j = 0; j < 4; j++) b[j] = Ks[tx*4+j][kk];
            #pragma unroll
            for (int i = 0; i < 4; i++)
                #pragma unroll
                for (int j = 0; j < 4; j++)
                    sreg[i][j] = fmaf(a[i], b[j], sreg[i][j]);
        }

        // Online softmax update (row stats replicated across the 16 tx lanes)
        #pragma unroll
        for (int i = 0; i < 4; i++) {
            float tm = fmaxf(fmaxf(sreg[i][0], sreg[i][1]),
                             fmaxf(sreg[i][2], sreg[i][3]));
            #pragma unroll
            for (int mask = 1; mask < 16; mask <<= 1)
                tm = fmaxf(tm, __shfl_xor_sync(0xffffffffu, tm, mask));
            const float mnew = fmaxf(m_i[i], tm);
            const float corr = __expf(m_i[i] - mnew);
            float rs = 0.f;
            #pragma unroll
            for (int j = 0; j < 4; j++) {
                sreg[i][j] = __expf(sreg[i][j] - mnew);
                rs += sreg[i][j];
            }
            #pragma unroll
            for (int mask = 1; mask < 16; mask <<= 1)
                rs += __shfl_xor_sync(0xffffffffu, rs, mask);
            l_i[i] = l_i[i] * corr + rs;
            m_i[i] = mnew;
            #pragma unroll
            for (int j = 0; j < 4; j++) o[i][j] *= corr;
        }

        // Stash P
        #pragma unroll
        for (int i = 0; i < 4; i++)
            #pragma unroll
            for (int j = 0; j < 4; j++)
                Ps[ty*4+i][tx*4+j] = sreg[i][j];
        __syncthreads();   // all Ks reads + Ps writes complete

        // Load V tile into Ks
        {
            const float* src = Vg + (size_t)(kbase + lr) * HDD + lc;
            #pragma unroll
            for (int u = 0; u < 4; u++) {
                float4 v4 = *(const float4*)(src + u*4);
                Ks[lr][lc + u*4 + 0] = v4.x;
                Ks[lr][lc + u*4 + 1] = v4.y;
                Ks[lr][lc + u*4 + 2] = v4.z;
                Ks[lr][lc + u*4 + 3] = v4.w;
            }
        }
        __syncthreads();

        // O += P @ V
        #pragma unroll 8
        for (int kk = 0; kk < 64; kk++) {
            float p[4], vv[4];
            #pragma unroll
            for (int i = 0; i < 4; i++) p[i] = Ps[ty*4+i][kk];
            #pragma unroll
            for (int j = 0; j < 4; j++) vv[j] = Ks[kk][tx*4+j];
            #pragma unroll
            for (int i = 0; i < 4; i++)
                #pragma unroll
                for (int j = 0; j < 4; j++)
                    o[i][j] = fmaf(p[i], vv[j], o[i][j]);
        }
        __syncthreads();   // done with Ks before next K load
    }

    // Normalize and write
    #pragma unroll
    for (int i = 0; i < 4; i++) {
        const float inv = 1.f / l_i[i];
        #pragma unroll
        for (int j = 0; j < 4; j++)
            Og[(size_t)(m0 + ty*4 + i) * HDD + tx*4 + j] = o[i][j] * inv;
    }
}

// ---------------------------------------------------------------------------
// Combine: x[b,s,d] = (attn*scale + bias) * (1 + mod*gate), with head-merge.
// ---------------------------------------------------------------------------
__global__ void combine_kernel(const float* __restrict__ dop,
                               const float* __restrict__ ser,
                               const float* __restrict__ nor,
                               const float* __restrict__ ace,
                               const float* __restrict__ asc,
                               const float* __restrict__ abi)
{
    const int idx = blockIdx.x * blockDim.x + threadIdx.x;
    if (idx >= BB*SS*DD) return;
    const float gate = 0.25f * (dop[0] + ser[0] + nor[0] + ace[0]);
    const int d = idx & (DD - 1);
    const int s = (idx >> 10) & (SS - 1);
    const int b = idx >> 21;
    const int h = d >> 6, hd = d & 63;
    const float a = g_attn[(((size_t)(b*HH + h))*SS + s)*HDD + hd];
    const float mo = g_mod[idx];
    g_x[idx] = (a * asc[0] + abi[0]) * (1.f + mo * gate);
}

// ---------------------------------------------------------------------------
extern "C" void kernel_launch(void* const* d_in, const int* in_sizes, int n_in,
                              void* d_out, int out_size)
{
    const float* query = (const float*)d_in[0];
    const float* Wq = (const float*)d_in[1];
    const float* bq = (const float*)d_in[2];
    const float* Wk = (const float*)d_in[3];
    const float* bk = (const float*)d_in[4];
    const float* Wv = (const float*)d_in[5];
    const float* bv = (const float*)d_in[6];
    const float* Wo = (const float*)d_in[7];
    const float* bo = (const float*)d_in[8];
    const float* Wm1 = (const float*)d_in[9];
    const float* bm1 = (const float*)d_in[10];
    const float* Wm2 = (const float*)d_in[11];
    const float* bm2 = (const float*)d_in[12];
    const float* dop = (const float*)d_in[13];
    const float* ser = (const float*)d_in[14];
    const float* nor = (const float*)d_in[15];
    const float* ace = (const float*)d_in[16];
    const float* asc = (const float*)d_in[17];
    const float* abi = (const float*)d_in[18];
    float* out = (float*)d_out;

    float *q, *k, *v, *hid, *mod, *x;
    cudaGetSymbolAddress((void**)&q,   g_q);
    cudaGetSymbolAddress((void**)&k,   g_k);
    cudaGetSymbolAddress((void**)&v,   g_v);
    cudaGetSymbolAddress((void**)&hid, g_hid);
    cudaGetSymbolAddress((void**)&mod, g_mod);
    cudaGetSymbolAddress((void**)&x,   g_x);

    const int M = BB * SS;          // 4096
    dim3 blk(256);

    // Q, K, V projections (fused head-split epilogue)
    {
        dim3 grid(DD/64, M/64);
        gemm_nt_kernel<<<grid, blk>>>(query, Wq, bq, q, M, DD, DD, 0, 1);
        gemm_nt_kernel<<<grid, blk>>>(query, Wk, bk, k, M, DD, DD, 0, 1);
        gemm_nt_kernel<<<grid, blk>>>(query, Wv, bv, v, M, DD, DD, 0, 1);
    }

    // Attention
    {
        dim3 grid(SS/64, BB*HH);
        attn_kernel<<<grid, blk>>>();
    }

    // Neuromod MLP
    {
        dim3 grid1(DM/64, M/64);
        gemm_nt_kernel<<<grid1, blk>>>(query, Wm1, bm1, hid, M, DM, DD, 1, 0);
        dim3 grid2(DD/64, M/64);
        gemm_nt_kernel<<<grid2, blk>>>(hid, Wm2, bm2, mod, M, DD, DM, 0, 0);
    }

    // Gate + merge heads
    {
        int n = BB*SS*DD;
        combine_kernel<<<(n + 255)/256, 256>>>(dop, ser, nor, ace, asc, abi);
    }

    // Output projection -> d_out
    {
        dim3 grid(DD/64, M/64);
        gemm_nt_kernel<<<grid, blk>>>(x, Wo, bo, out, M, DD, DD, 0, 0);
    }
}

// round 4
// speedup vs baseline: 2.7544x; 2.7544x over previous
#include <cuda_runtime.h>
#include <cstdint>
#include <cstddef>

// Problem constants
#define BB 2
#define SS 2048
#define DD 1024
#define HH 16
#define HDD 64
#define DM 256  // D/4

// Scratch (device globals — no runtime allocation allowed)
__device__ float g_q[BB*HH*SS*HDD];
__device__ float g_k[BB*HH*SS*HDD];
__device__ float g_v[BB*HH*SS*HDD];
__device__ float g_attn[BB*HH*SS*HDD];
__device__ float g_hid[BB*SS*DM];
__device__ float g_mod[BB*SS*DD];
__device__ float g_x[BB*SS*DD];

// ===========================================================================
// Helpers (arch-agnostic PTX only: mma.sync tf32, cp.async — no tcgen05!)
// ===========================================================================
__device__ __forceinline__ uint32_t smem_u32(const void* p) {
    uint32_t a;
    asm("{ .reg .u64 t; cvta.to.shared.u64 t, %1; cvt.u32.u64 %0, t; }"
        : "=r"(a) : "l"(p));
    return a;
}

__device__ __forceinline__ uint32_t f2tf(float f) {
    uint32_t u;
    asm("cvt.rna.tf32.f32 %0, %1;" : "=r"(u) : "f"(f));
    return u;
}

// D += A @ B  (m16n8k8 tf32, A row-major, B col-major)
__device__ __forceinline__ void mma_tf32(float (&d)[4], const uint32_t (&a)[4],
                                         const uint32_t (&b)[2]) {
    asm volatile(
        "mma.sync.aligned.m16n8k8.row.col.f32.tf32.tf32.f32 "
        "{%0,%1,%2,%3}, {%4,%5,%6,%7}, {%8,%9}, {%0,%1,%2,%3};"
        : "+f"(d[0]), "+f"(d[1]), "+f"(d[2]), "+f"(d[3])
        : "r"(a[0]), "r"(a[1]), "r"(a[2]), "r"(a[3]), "r"(b[0]), "r"(b[1]));
}

__device__ __forceinline__ void cp16(uint32_t dst, const void* src) {
    asm volatile("cp.async.ca.shared.global [%0], [%1], 16;"
                 :: "r"(dst), "l"(src));
}
#define CP_COMMIT() asm volatile("cp.async.commit_group;" ::: "memory")
#define CP_WAIT1()  asm volatile("cp.async.wait_group 1;"  ::: "memory")

// ===========================================================================
// tf32 MMA GEMM: C[M,N] = A[M,K] @ W[N,K]^T + bias[N]
// 128x128 CTA tile, 256 threads (8 warps), warp tile 32x64.
// BK=16, double-buffered cp.async. relu / head-split epilogue options.
// ===========================================================================
#define PAD 20   // floats per smem row (16 data + 4 pad; keeps 16B alignment)

__global__ void __launch_bounds__(256) gemm_mma_kernel(
    const float* __restrict__ A, const float* __restrict__ W,
    const float* __restrict__ bias, float* __restrict__ C,
    int M, int N, int K, int relu, int split)
{
    __shared__ float As[2][128*PAD];
    __shared__ float Bs[2][128*PAD];

    const int tid = threadIdx.x;
    const int wid = tid >> 5;
    const int lane = tid & 31;
    const int gr = lane >> 2;       // group row 0..7
    const int tc = lane & 3;        // thread col 0..3
    const int warp_m = wid & 3;     // 4 warps along M
    const int warp_n = wid >> 2;    // 2 warps along N
    const int m0 = blockIdx.y << 7;
    const int n0 = blockIdx.x << 7;

    const uint32_t sA[2] = { smem_u32(As[0]), smem_u32(As[1]) };
    const uint32_t sB[2] = { smem_u32(Bs[0]), smem_u32(Bs[1]) };

    float acc[2][8][4];
    #pragma unroll
    for (int mi = 0; mi < 2; mi++)
        #pragma unroll
        for (int nj = 0; nj < 8; nj++)
            #pragma unroll
            for (int q = 0; q < 4; q++) acc[mi][nj][q] = 0.f;

    const int KB = K >> 4;

    // Issue tile loads for block kb into buffer buf
    auto issue = [&](int kb, int buf) {
        #pragma unroll
        for (int i = 0; i < 2; i++) {
            const int ch = tid + (i << 8);       // 0..511
            const int row = ch >> 2, c4 = ch & 3;
            cp16(sA[buf] + (uint32_t)(row*PAD + c4*4)*4,
                 A + (size_t)(m0 + row)*K + kb*16 + c4*4);
            cp16(sB[buf] + (uint32_t)(row*PAD + c4*4)*4,
                 W + (size_t)(n0 + row)*K + kb*16 + c4*4);
        }
    };

    issue(0, 0);
    CP_COMMIT();

    for (int kb = 0; kb < KB; kb++) {
        const int buf = kb & 1;
        if (kb + 1 < KB) issue(kb + 1, buf ^ 1);
        CP_COMMIT();
        CP_WAIT1();
        __syncthreads();

        const float* a_s = As[buf];
        const float* b_s = Bs[buf];
        #pragma unroll
        for (int ks = 0; ks < 16; ks += 8) {
            uint32_t af[2][4];
            #pragma unroll
            for (int mi = 0; mi < 2; mi++) {
                const int r = warp_m*32 + mi*16 + gr;
                af[mi][0] = f2tf(a_s[r*PAD + ks + tc]);
                af[mi][1] = f2tf(a_s[(r+8)*PAD + ks + tc]);
                af[mi][2] = f2tf(a_s[r*PAD + ks + tc + 4]);
                af[mi][3] = f2tf(a_s[(r+8)*PAD + ks + tc + 4]);
            }
            #pragma unroll
            for (int nj = 0; nj < 8; nj++) {
                const int n = warp_n*64 + nj*8 + gr;
                uint32_t bf[2];
                bf[0] = f2tf(b_s[n*PAD + ks + tc]);
                bf[1] = f2tf(b_s[n*PAD + ks + tc + 4]);
                mma_tf32(acc[0][nj], af[0], bf);
                mma_tf32(acc[1][nj], af[1], bf);
            }
        }
        __syncthreads();
    }

    // Epilogue
    #pragma unroll
    for (int mi = 0; mi < 2; mi++) {
        const int row = m0 + warp_m*32 + mi*16 + gr;
        #pragma unroll
        for (int nj = 0; nj < 8; nj++) {
            const int col = n0 + warp_n*64 + nj*8 + 2*tc;
            const float b0 = bias[col], b1 = bias[col+1];
            float2 v0 = make_float2(acc[mi][nj][0] + b0, acc[mi][nj][1] + b1);
            float2 v1 = make_float2(acc[mi][nj][2] + b0, acc[mi][nj][3] + b1);
            if (relu) {
                v0.x = fmaxf(v0.x, 0.f); v0.y = fmaxf(v0.y, 0.f);
                v1.x = fmaxf(v1.x, 0.f); v1.y = fmaxf(v1.y, 0.f);
            }
            if (split) {
                const int b = row >> 11, s = row & (SS - 1);
                const int h = col >> 6, hd = col & 63;
                float* base = g_q; // placeholder, C points into split target
                (void)base;
                float* d0 = C + (((size_t)(b*HH + h))*SS + s)*HDD + hd;
                const int rb = (row+8) >> 11, rs = (row+8) & (SS - 1);
                float* d1 = C + (((size_t)(rb*HH + h))*SS + rs)*HDD + hd;
                *(float2*)d0 = v0;
                *(float2*)d1 = v1;
            } else {
                *(float2*)(C + (size_t)row*N + col) = v0;
                *(float2*)(C + (size_t)(row+8)*N + col) = v1;
            }
        }
    }
}

// ===========================================================================
// Flash attention with tf32 MMA.
// CTA: 128 q rows for one (b,h); 8 warps, each warp owns 16 q rows.
// Loop over 32 key tiles of 64: S=QK^T (MMA) -> smem -> SIMT online softmax
// -> P@V (MMA) into register O, rescaled by corr each tile.
// Dynamic smem: Ks[64][68], Vs[64][68], Ssm[128][68], stats[3*128].
// ===========================================================================
#define AKP 68
#define ATT_SMEM_BYTES ((64*AKP*2 + 128*AKP + 3*128) * 4)

__global__ void __launch_bounds__(256) attn_mma_kernel()
{
    extern __shared__ float sm[];
    float* Ks   = sm;                       // tf32 bits
    float* Vs   = Ks + 64*AKP;              // tf32 bits
    float* Ssm  = Vs + 64*AKP;              // fp32 S, then tf32 P
    float* m_s  = Ssm + 128*AKP;
    float* l_s  = m_s + 128;
    float* cr_s = l_s + 128;

    const int tid = threadIdx.x;
    const int wid = tid >> 5;
    const int lane = tid & 31;
    const int gr = lane >> 2;
    const int tc = lane & 3;

    const int bh = blockIdx.y;
    const int m0 = blockIdx.x << 7;
    const float* Qg = g_q + (size_t)bh * SS * HDD;
    const float* Kg = g_k + (size_t)bh * SS * HDD;
    const float* Vg = g_v + (size_t)bh * SS * HDD;
    float*       Og = g_attn + (size_t)bh * SS * HDD;

    // Q fragments: warp's 16 rows x 64 cols, register resident, pre-scaled
    uint32_t qa[8][4];
    {
        const float scale = 0.125f;
        const float* q0 = Qg + (size_t)(m0 + wid*16 + gr) * HDD;
        const float* q1 = q0 + 8 * HDD;
        #pragma unroll
        for (int kf = 0; kf < 8; kf++) {
            qa[kf][0] = f2tf(q0[kf*8 + tc] * scale);
            qa[kf][1] = f2tf(q1[kf*8 + tc] * scale);
            qa[kf][2] = f2tf(q0[kf*8 + tc + 4] * scale);
            qa[kf][3] = f2tf(q1[kf*8 + tc + 4] * scale);
        }
    }

    if (tid < 128) { m_s[tid] = -1e30f; l_s[tid] = 0.f; }

    float o[8][4];
    #pragma unroll
    for (int nj = 0; nj < 8; nj++)
        #pragma unroll
        for (int q = 0; q < 4; q++) o[nj][q] = 0.f;

    const int lrow = tid >> 2;           // 0..63 (K/V load row)
    const int lcol = (tid & 3) << 4;     // 0,16,32,48

    for (int kt = 0; kt < SS/64; kt++) {
        const int kbase = kt << 6;
        __syncthreads();   // previous iteration's reads of Ks/Vs/Ssm done

        // Load K and V tiles (convert to tf32 bits on the way in)
        {
            const float* ksrc = Kg + (size_t)(kbase + lrow)*HDD + lcol;
            const float* vsrc = Vg + (size_t)(kbase + lrow)*HDD + lcol;
            uint32_t* kd = (uint32_t*)(Ks + lrow*AKP + lcol);
            uint32_t* vd = (uint32_t*)(Vs + lrow*AKP + lcol);
            #pragma unroll
            for (int u = 0; u < 4; u++) {
                float4 kv = *(const float4*)(ksrc + u*4);
                float4 vv = *(const float4*)(vsrc + u*4);
                ((uint4*)kd)[u] = make_uint4(f2tf(kv.x), f2tf(kv.y), f2tf(kv.z), f2tf(kv.w));
                ((uint4*)vd)[u] = make_uint4(f2tf(vv.x), f2tf(vv.y), f2tf(vv.z), f2tf(vv.w));
            }
        }
        __syncthreads();

        // S = Q @ K^T  (warp: 16 rows x 64 keys)
        float sacc[8][4];
        #pragma unroll
        for (int nj = 0; nj < 8; nj++)
            #pragma unroll
            for (int q = 0; q < 4; q++) sacc[nj][q] = 0.f;
        #pragma unroll
        for (int kf = 0; kf < 8; kf++) {
            #pragma unroll
            for (int nj = 0; nj < 8; nj++) {
                uint32_t bf[2];
                const uint32_t* kb = (const uint32_t*)(Ks + (nj*8 + gr)*AKP + kf*8 + tc);
                bf[0] = kb[0];
                bf[1] = kb[4];
                mma_tf32(sacc[nj], qa[kf], bf);
            }
        }

        // Store S tile
        {
            const int row0 = wid*16 + gr;
            #pragma unroll
            for (int nj = 0; nj < 8; nj++) {
                *(float2*)(Ssm + row0*AKP + nj*8 + 2*tc) =
                    make_float2(sacc[nj][0], sacc[nj][1]);
                *(float2*)(Ssm + (row0+8)*AKP + nj*8 + 2*tc) =
                    make_float2(sacc[nj][2], sacc[nj][3]);
            }
        }
        __syncthreads();

        // SIMT online softmax: 2 threads per row, 32 cols each
        {
            const int row = tid >> 1, half = tid & 1;
            float* Srow = Ssm + row*AKP + half*32;
            float mx = -1e30f;
            #pragma unroll
            for (int j = 0; j < 32; j++) mx = fmaxf(mx, Srow[j]);
            mx = fmaxf(mx, __shfl_xor_sync(0xffffffffu, mx, 1));
            const float mold = m_s[row];
            const float mnew = fmaxf(mold, mx);
            const float corr = __expf(mold - mnew);
            float sum = 0.f;
            #pragma unroll
            for (int j = 0; j < 32; j++) {
                const float p = __expf(Srow[j] - mnew);
                sum += p;
                ((uint32_t*)Srow)[j] = f2tf(p);
            }
            sum += __shfl_xor_sync(0xffffffffu, sum, 1);
            if (!half) {
                m_s[row] = mnew;
                l_s[row] = l_s[row]*corr + sum;
                cr_s[row] = corr;
            }
        }
        __syncthreads();

        // Rescale O by corr
        {
            const float c0 = cr_s[wid*16 + gr];
            const float c1 = cr_s[wid*16 + gr + 8];
            #pragma unroll
            for (int nj = 0; nj < 8; nj++) {
                o[nj][0] *= c0; o[nj][1] *= c0;
                o[nj][2] *= c1; o[nj][3] *= c1;
            }
        }

        // O += P @ V  (warp: 16 rows x 64 hd)
        #pragma unroll
        for (int kf = 0; kf < 8; kf++) {
            uint32_t pa[4];
            const uint32_t* pr = (const uint32_t*)(Ssm + (wid*16 + gr)*AKP + kf*8 + tc);
            pa[0] = pr[0];
            pa[1] = pr[8*AKP];
            pa[2] = pr[4];
            pa[3] = pr[8*AKP + 4];
            #pragma unroll
            for (int nj = 0; nj < 8; nj++) {
                uint32_t vb[2];
                const uint32_t* vr = (const uint32_t*)(Vs + (kf*8 + tc)*AKP + nj*8 + gr);
                vb[0] = vr[0];
                vb[1] = vr[4*AKP];
                mma_tf32(o[nj], pa, vb);
            }
        }
    }
    __syncthreads();

    // Normalize and write
    {
        const int row0 = wid*16 + gr;
        const float inv0 = 1.f / l_s[row0];
        const float inv1 = 1.f / l_s[row0 + 8];
        #pragma unroll
        for (int nj = 0; nj < 8; nj++) {
            const int col = nj*8 + 2*tc;
            *(float2*)(Og + (size_t)(m0 + row0)*HDD + col) =
                make_float2(o[nj][0]*inv0, o[nj][1]*inv0);
            *(float2*)(Og + (size_t)(m0 + row0 + 8)*HDD + col) =
                make_float2(o[nj][2]*inv1, o[nj][3]*inv1);
        }
    }
}

// ---------------------------------------------------------------------------
// Combine: x[b,s,d] = (attn*scale + bias) * (1 + mod*gate), with head-merge.
// ---------------------------------------------------------------------------
__global__ void combine_kernel(const float* __restrict__ dop,
                               const float* __restrict__ ser,
                               const float* __restrict__ nor,
                               const float* __restrict__ ace,
                               const float* __restrict__ asc,
                               const float* __restrict__ abi)
{
    const int idx = blockIdx.x * blockDim.x + threadIdx.x;
    if (idx >= BB*SS*DD) return;
    const float gate = 0.25f * (dop[0] + ser[0] + nor[0] + ace[0]);
    const int d = idx & (DD - 1);
    const int s = (idx >> 10) & (SS - 1);
    const int b = idx >> 21;
    const int h = d >> 6, hd = d & 63;
    const float a = g_attn[(((size_t)(b*HH + h))*SS + s)*HDD + hd];
    const float mo = g_mod[idx];
    g_x[idx] = (a * asc[0] + abi[0]) * (1.f + mo * gate);
}

// ---------------------------------------------------------------------------
extern "C" void kernel_launch(void* const* d_in, const int* in_sizes, int n_in,
                              void* d_out, int out_size)
{
    const float* query = (const float*)d_in[0];
    const float* Wq = (const float*)d_in[1];
    const float* bq = (const float*)d_in[2];
    const float* Wk = (const float*)d_in[3];
    const float* bk = (const float*)d_in[4];
    const float* Wv = (const float*)d_in[5];
    const float* bv = (const float*)d_in[6];
    const float* Wo = (const float*)d_in[7];
    const float* bo = (const float*)d_in[8];
    const float* Wm1 = (const float*)d_in[9];
    const float* bm1 = (const float*)d_in[10];
    const float* Wm2 = (const float*)d_in[11];
    const float* bm2 = (const float*)d_in[12];
    const float* dop = (const float*)d_in[13];
    const float* ser = (const float*)d_in[14];
    const float* nor = (const float*)d_in[15];
    const float* ace = (const float*)d_in[16];
    const float* asc = (const float*)d_in[17];
    const float* abi = (const float*)d_in[18];
    float* out = (float*)d_out;

    float *q, *k, *v, *hid, *mod, *x;
    cudaGetSymbolAddress((void**)&q,   g_q);
    cudaGetSymbolAddress((void**)&k,   g_k);
    cudaGetSymbolAddress((void**)&v,   g_v);
    cudaGetSymbolAddress((void**)&hid, g_hid);
    cudaGetSymbolAddress((void**)&mod, g_mod);
    cudaGetSymbolAddress((void**)&x,   g_x);

    static int attrs_set = 0;
    if (!attrs_set) {
        cudaFuncSetAttribute(attn_mma_kernel,
            cudaFuncAttributeMaxDynamicSharedMemorySize, ATT_SMEM_BYTES);
        attrs_set = 1;
    }

    const int M = BB * SS;          // 4096
    dim3 blk(256);

    // Q, K, V projections (tf32 MMA, fused head-split epilogue)
    {
        dim3 grid(DD/128, M/128);
        gemm_mma_kernel<<<grid, blk>>>(query, Wq, bq, q, M, DD, DD, 0, 1);
        gemm_mma_kernel<<<grid, blk>>>(query, Wk, bk, k, M, DD, DD, 0, 1);
        gemm_mma_kernel<<<grid, blk>>>(query, Wv, bv, v, M, DD, DD, 0, 1);
    }

    // Attention (tf32 MMA flash)
    {
        dim3 grid(SS/128, BB*HH);
        attn_mma_kernel<<<grid, blk, ATT_SMEM_BYTES>>>();
    }

    // Neuromod MLP (tf32 MMA)
    {
        dim3 grid1(DM/128, M/128);
        gemm_mma_kernel<<<grid1, blk>>>(query, Wm1, bm1, hid, M, DM, DD, 1, 0);
        dim3 grid2(DD/128, M/128);
        gemm_mma_kernel<<<grid2, blk>>>(hid, Wm2, bm2, mod, M, DD, DM, 0, 0);
    }

    // Gate + merge heads
    {
        int n = BB*SS*DD;
        combine_kernel<<<(n + 255)/256, 256>>>(dop, ser, nor, ace, asc, abi);
    }

    // Output projection -> d_out (tf32 MMA)
    {
        dim3 grid(DD/128, M/128);
        gemm_mma_kernel<<<grid, blk>>>(x, Wo, bo, out, M, DD, DD, 0, 0);
    }
}

// round 7
// speedup vs baseline: 3.2987x; 1.1976x over previous
#include <cuda_runtime.h>
#include <cstdint>
#include <cstddef>

// Problem constants
#define BB 2
#define SS 2048
#define DD 1024
#define HH 16
#define HDD 64
#define DM 256  // D/4

// Scratch (device globals — no runtime allocation allowed)
// g_q: tf32 bits, pre-scaled by 0.125. g_k/g_v: tf32 bits.
__device__ float g_q[BB*HH*SS*HDD];
__device__ float g_k[BB*HH*SS*HDD];
__device__ float g_v[BB*HH*SS*HDD];
__device__ float g_attn[BB*HH*SS*HDD];
__device__ float g_hid[BB*SS*DM];
__device__ float g_mod[BB*SS*DD];
__device__ float g_x[BB*SS*DD];

// ===========================================================================
// Helpers (arch-agnostic PTX only: mma.sync tf32, cp.async — no tcgen05!)
// ===========================================================================
__device__ __forceinline__ uint32_t smem_u32(const void* p) {
    uint32_t a;
    asm("{ .reg .u64 t; cvta.to.shared.u64 t, %1; cvt.u32.u64 %0, t; }"
        : "=r"(a) : "l"(p));
    return a;
}

__device__ __forceinline__ uint32_t f2tf(float f) {
    uint32_t u;
    asm("cvt.rna.tf32.f32 %0, %1;" : "=r"(u) : "f"(f));
    return u;
}

// D += A @ B  (m16n8k8 tf32, A row-major, B col-major)
__device__ __forceinline__ void mma_tf32(float (&d)[4], const uint32_t (&a)[4],
                                         const uint32_t (&b)[2]) {
    asm volatile(
        "mma.sync.aligned.m16n8k8.row.col.f32.tf32.tf32.f32 "
        "{%0,%1,%2,%3}, {%4,%5,%6,%7}, {%8,%9}, {%0,%1,%2,%3};"
        : "+f"(d[0]), "+f"(d[1]), "+f"(d[2]), "+f"(d[3])
        : "r"(a[0]), "r"(a[1]), "r"(a[2]), "r"(a[3]), "r"(b[0]), "r"(b[1]));
}

__device__ __forceinline__ void cp16(uint32_t dst, const void* src) {
    asm volatile("cp.async.ca.shared.global [%0], [%1], 16;"
                 :: "r"(dst), "l"(src));
}
#define CP_COMMIT() asm volatile("cp.async.commit_group;" ::: "memory")
#define CP_WAIT1()  asm volatile("cp.async.wait_group 1;"  ::: "memory")
#define CP_WAIT0()  asm volatile("cp.async.wait_group 0;"  ::: "memory")

// ===========================================================================
// tf32 MMA GEMM: C[M,N] = A[M,K] @ W[N,K]^T + bias[N]
// 128x128 CTA tile, 256 threads (8 warps), warp tile 32x64.
// BK=16, double-buffered cp.async.
// relu: ReLU. split: head-split layout. conv: store f2tf(val*conv) bits.
// ===========================================================================
#define PAD 20   // floats per smem row (16 data + 4 pad; keeps 16B alignment)

__global__ void __launch_bounds__(256) gemm_mma_kernel(
    const float* __restrict__ A, const float* __restrict__ W,
    const float* __restrict__ bias, float* __restrict__ C,
    int M, int N, int K, int relu, int split, float conv)
{
    __shared__ float As[2][128*PAD];
    __shared__ float Bs[2][128*PAD];

    const int tid = threadIdx.x;
    const int wid = tid >> 5;
    const int lane = tid & 31;
    const int gr = lane >> 2;       // group row 0..7
    const int tc = lane & 3;        // thread col 0..3
    const int warp_m = wid & 3;     // 4 warps along M
    const int warp_n = wid >> 2;    // 2 warps along N
    const int m0 = blockIdx.y << 7;
    const int n0 = blockIdx.x << 7;

    const uint32_t sA[2] = { smem_u32(As[0]), smem_u32(As[1]) };
    const uint32_t sB[2] = { smem_u32(Bs[0]), smem_u32(Bs[1]) };

    float acc[2][8][4];
    #pragma unroll
    for (int mi = 0; mi < 2; mi++)
        #pragma unroll
        for (int nj = 0; nj < 8; nj++)
            #pragma unroll
            for (int q = 0; q < 4; q++) acc[mi][nj][q] = 0.f;

    const int KB = K >> 4;

    auto issue = [&](int kb, int buf) {
        #pragma unroll
        for (int i = 0; i < 2; i++) {
            const int ch = tid + (i << 8);       // 0..511
            const int row = ch >> 2, c4 = ch & 3;
            cp16(sA[buf] + (uint32_t)(row*PAD + c4*4)*4,
                 A + (size_t)(m0 + row)*K + kb*16 + c4*4);
            cp16(sB[buf] + (uint32_t)(row*PAD + c4*4)*4,
                 W + (size_t)(n0 + row)*K + kb*16 + c4*4);
        }
    };

    issue(0, 0);
    CP_COMMIT();

    for (int kb = 0; kb < KB; kb++) {
        const int buf = kb & 1;
        if (kb + 1 < KB) issue(kb + 1, buf ^ 1);
        CP_COMMIT();
        CP_WAIT1();
        __syncthreads();

        const float* a_s = As[buf];
        const float* b_s = Bs[buf];
        #pragma unroll
        for (int ks = 0; ks < 16; ks += 8) {
            uint32_t af[2][4];
            #pragma unroll
            for (int mi = 0; mi < 2; mi++) {
                const int r = warp_m*32 + mi*16 + gr;
                af[mi][0] = f2tf(a_s[r*PAD + ks + tc]);
                af[mi][1] = f2tf(a_s[(r+8)*PAD + ks + tc]);
                af[mi][2] = f2tf(a_s[r*PAD + ks + tc + 4]);
                af[mi][3] = f2tf(a_s[(r+8)*PAD + ks + tc + 4]);
            }
            #pragma unroll
            for (int nj = 0; nj < 8; nj++) {
                const int n = warp_n*64 + nj*8 + gr;
                uint32_t bf[2];
                bf[0] = f2tf(b_s[n*PAD + ks + tc]);
                bf[1] = f2tf(b_s[n*PAD + ks + tc + 4]);
                mma_tf32(acc[0][nj], af[0], bf);
                mma_tf32(acc[1][nj], af[1], bf);
            }
        }
        __syncthreads();
    }

    // Epilogue
    #pragma unroll
    for (int mi = 0; mi < 2; mi++) {
        const int row = m0 + warp_m*32 + mi*16 + gr;
        #pragma unroll
        for (int nj = 0; nj < 8; nj++) {
            const int col = n0 + warp_n*64 + nj*8 + 2*tc;
            const float b0 = bias[col], b1 = bias[col+1];
            float2 v0 = make_float2(acc[mi][nj][0] + b0, acc[mi][nj][1] + b1);
            float2 v1 = make_float2(acc[mi][nj][2] + b0, acc[mi][nj][3] + b1);
            if (relu) {
                v0.x = fmaxf(v0.x, 0.f); v0.y = fmaxf(v0.y, 0.f);
                v1.x = fmaxf(v1.x, 0.f); v1.y = fmaxf(v1.y, 0.f);
            }
            if (conv != 0.f) {   // store tf32 bits (optionally pre-scaled)
                v0.x = __uint_as_float(f2tf(v0.x * conv));
                v0.y = __uint_as_float(f2tf(v0.y * conv));
                v1.x = __uint_as_float(f2tf(v1.x * conv));
                v1.y = __uint_as_float(f2tf(v1.y * conv));
            }
            if (split) {
                const int b = row >> 11, s = row & (SS - 1);
                const int h = col >> 6, hd = col & 63;
                float* d0 = C + (((size_t)(b*HH + h))*SS + s)*HDD + hd;
                const int rb = (row+8) >> 11, rs = (row+8) & (SS - 1);
                float* d1 = C + (((size_t)(rb*HH + h))*SS + rs)*HDD + hd;
                *(float2*)d0 = v0;
                *(float2*)d1 = v1;
            } else {
                *(float2*)(C + (size_t)row*N + col) = v0;
                *(float2*)(C + (size_t)(row+8)*N + col) = v1;
            }
        }
    }
}

// ===========================================================================
// Flash attention, tf32 MMA, register online-softmax, cp.async double-buffer.
// CTA: 128 q rows of one (b,h); 8 warps x 16 rows. K/V pre-converted tf32.
// Per 64-key tile: S=QK^T (MMA, acc in regs) -> softmax in regs (shfl quad
// reduction) -> P (tf32) to smem -> O += P@V (MMA). 2 syncs/tile.
// smem: Kd[2][64*AKP] Vd[2][64*AKP] Psm[128*AKP]
// ===========================================================================
#define AKP 68
#define ATT_KV_TILE (64*AKP)
#define ATT_SMEM_BYTES ((2*ATT_KV_TILE*2 + 128*AKP) * 4)

__global__ void __launch_bounds__(256, 2) attn_mma_kernel()
{
    extern __shared__ float sm[];
    float* Kd = sm;                           // [2][64*AKP] tf32 bits
    float* Vd = sm + 2*ATT_KV_TILE;           // [2][64*AKP] tf32 bits
    float* Psm = sm + 4*ATT_KV_TILE;          // [128*AKP] tf32 bits

    const int tid = threadIdx.x;
    const int wid = tid >> 5;
    const int lane = tid & 31;
    const int gr = lane >> 2;
    const int tc = lane & 3;

    const int bh = blockIdx.y;
    const int m0 = blockIdx.x << 7;
    const float* Qg = g_q + (size_t)bh * SS * HDD;
    const float* Kg = g_k + (size_t)bh * SS * HDD;
    const float* Vg = g_v + (size_t)bh * SS * HDD;
    float*       Og = g_attn + (size_t)bh * SS * HDD;

    const uint32_t sK = smem_u32(Kd);
    const uint32_t sV = smem_u32(Vd);

    // Issue async copy of key tile kt into buffer buf (K: 16KB, V: 16KB)
    auto issue_kv = [&](int kt, int buf) {
        const int kbase = kt << 6;
        #pragma unroll
        for (int i = 0; i < 4; i++) {
            const int ch = tid + (i << 8);          // 0..1023
            const int row = ch >> 4, c16 = ch & 15; // 16 x 16B per 256B row
            const uint32_t doff = (uint32_t)(buf*ATT_KV_TILE + row*AKP + c16*4)*4;
            const size_t soff = (size_t)(kbase + row)*HDD + c16*4;
            cp16(sK + doff, Kg + soff);
            cp16(sV + doff, Vg + soff);
        }
    };

    // Q fragments: warp's 16 rows x 64 cols (already tf32 bits, pre-scaled)
    uint32_t qa[8][4];
    {
        const uint32_t* q0 = (const uint32_t*)(Qg + (size_t)(m0 + wid*16 + gr) * HDD);
        const uint32_t* q1 = q0 + 8 * HDD;
        #pragma unroll
        for (int kf = 0; kf < 8; kf++) {
            qa[kf][0] = q0[kf*8 + tc];
            qa[kf][1] = q1[kf*8 + tc];
            qa[kf][2] = q0[kf*8 + tc + 4];
            qa[kf][3] = q1[kf*8 + tc + 4];
        }
    }

    float m0s = -1e30f, m1s = -1e30f, l0s = 0.f, l1s = 0.f;
    float o[8][4];
    #pragma unroll
    for (int nj = 0; nj < 8; nj++)
        #pragma unroll
        for (int q = 0; q < 4; q++) o[nj][q] = 0.f;

    issue_kv(0, 0);
    CP_COMMIT();

    const int NT = SS / 64;
    for (int kt = 0; kt < NT; kt++) {
        const int buf = kt & 1;
        CP_WAIT0();
        __syncthreads();   // tile kt ready; prev iter's reads of buf^1 done
        if (kt + 1 < NT) { issue_kv(kt + 1, buf ^ 1); CP_COMMIT(); }

        const float* Ks = Kd + buf*ATT_KV_TILE;
        const float* Vs = Vd + buf*ATT_KV_TILE;

        // S = Q @ K^T  (warp: 16 rows x 64 keys)
        float sacc[8][4];
        #pragma unroll
        for (int nj = 0; nj < 8; nj++)
            #pragma unroll
            for (int q = 0; q < 4; q++) sacc[nj][q] = 0.f;
        #pragma unroll
        for (int kf = 0; kf < 8; kf++) {
            #pragma unroll
            for (int nj = 0; nj < 8; nj++) {
                const uint32_t* kb = (const uint32_t*)(Ks + (nj*8 + gr)*AKP + kf*8 + tc);
                uint32_t bf[2] = { kb[0], kb[4] };
                mma_tf32(sacc[nj], qa[kf], bf);
            }
        }

        // Register online softmax. Rows gr (elems 0,1) and gr+8 (elems 2,3);
        // each row is spread across the 4 lanes of a quad (tc) -> shfl reduce.
        float mx0 = -1e30f, mx1 = -1e30f;
        #pragma unroll
        for (int nj = 0; nj < 8; nj++) {
            mx0 = fmaxf(mx0, fmaxf(sacc[nj][0], sacc[nj][1]));
            mx1 = fmaxf(mx1, fmaxf(sacc[nj][2], sacc[nj][3]));
        }
        mx0 = fmaxf(mx0, __shfl_xor_sync(0xffffffffu, mx0, 1));
        mx0 = fmaxf(mx0, __shfl_xor_sync(0xffffffffu, mx0, 2));
        mx1 = fmaxf(mx1, __shfl_xor_sync(0xffffffffu, mx1, 1));
        mx1 = fmaxf(mx1, __shfl_xor_sync(0xffffffffu, mx1, 2));

        const float mn0 = fmaxf(m0s, mx0);
        const float mn1 = fmaxf(m1s, mx1);
        const float c0 = __expf(m0s - mn0);
        const float c1 = __expf(m1s - mn1);
        float s0 = 0.f, s1 = 0.f;

        const int prow = wid*16 + gr;
        #pragma unroll
        for (int nj = 0; nj < 8; nj++) {
            const float p00 = __expf(sacc[nj][0] - mn0);
            const float p01 = __expf(sacc[nj][1] - mn0);
            const float p10 = __expf(sacc[nj][2] - mn1);
            const float p11 = __expf(sacc[nj][3] - mn1);
            s0 += p00 + p01;
            s1 += p10 + p11;
            *(uint2*)(Psm + prow*AKP + nj*8 + 2*tc) =
                make_uint2(f2tf(p00), f2tf(p01));
            *(uint2*)(Psm + (prow+8)*AKP + nj*8 + 2*tc) =
                make_uint2(f2tf(p10), f2tf(p11));
        }
        s0 += __shfl_xor_sync(0xffffffffu, s0, 1);
        s0 += __shfl_xor_sync(0xffffffffu, s0, 2);
        s1 += __shfl_xor_sync(0xffffffffu, s1, 1);
        s1 += __shfl_xor_sync(0xffffffffu, s1, 2);
        l0s = l0s*c0 + s0;  m0s = mn0;
        l1s = l1s*c1 + s1;  m1s = mn1;

        // Rescale O
        #pragma unroll
        for (int nj = 0; nj < 8; nj++) {
            o[nj][0] *= c0; o[nj][1] *= c0;
            o[nj][2] *= c1; o[nj][3] *= c1;
        }
        __syncthreads();   // P visible to whole warp set

        // O += P @ V  (warp: 16 rows x 64 hd)
        #pragma unroll
        for (int kf = 0; kf < 8; kf++) {
            uint32_t pa[4];
            const uint32_t* pr = (const uint32_t*)(Psm + prow*AKP + kf*8 + tc);
            pa[0] = pr[0];
            pa[1] = pr[8*AKP];
            pa[2] = pr[4];
            pa[3] = pr[8*AKP + 4];
            #pragma unroll
            for (int nj = 0; nj < 8; nj++) {
                const uint32_t* vr = (const uint32_t*)(Vs + (kf*8 + tc)*AKP + nj*8 + gr);
                uint32_t vb[2] = { vr[0], vr[4*AKP] };
                mma_tf32(o[nj], pa, vb);
            }
        }
    }

    // Normalize and write
    {
        const int row0 = wid*16 + gr;
        const float inv0 = 1.f / l0s;
        const float inv1 = 1.f / l1s;
        #pragma unroll
        for (int nj = 0; nj < 8; nj++) {
            const int col = nj*8 + 2*tc;
            *(float2*)(Og + (size_t)(m0 + row0)*HDD + col) =
                make_float2(o[nj][0]*inv0, o[nj][1]*inv0);
            *(float2*)(Og + (size_t)(m0 + row0 + 8)*HDD + col) =
                make_float2(o[nj][2]*inv1, o[nj][3]*inv1);
        }
    }
}

// ---------------------------------------------------------------------------
// Combine: x[b,s,d] = (attn*scale + bias) * (1 + mod*gate), with head-merge.
// ---------------------------------------------------------------------------
__global__ void combine_kernel(const float* __restrict__ dop,
                               const float* __restrict__ ser,
                               const float* __restrict__ nor,
                               const float* __restrict__ ace,
                               const float* __restrict__ asc,
                               const float* __restrict__ abi)
{
    const int idx = blockIdx.x * blockDim.x + threadIdx.x;
    if (idx >= BB*SS*DD) return;
    const float gate = 0.25f * (dop[0] + ser[0] + nor[0] + ace[0]);
    const int d = idx & (DD - 1);
    const int s = (idx >> 10) & (SS - 1);
    const int b = idx >> 21;
    const int h = d >> 6, hd = d & 63;
    const float a = g_attn[(((size_t)(b*HH + h))*SS + s)*HDD + hd];
    const float mo = g_mod[idx];
    g_x[idx] = (a * asc[0] + abi[0]) * (1.f + mo * gate);
}

// ---------------------------------------------------------------------------
extern "C" void kernel_launch(void* const* d_in, const int* in_sizes, int n_in,
                              void* d_out, int out_size)
{
    const float* query = (const float*)d_in[0];
    const float* Wq = (const float*)d_in[1];
    const float* bq = (const float*)d_in[2];
    const float* Wk = (const float*)d_in[3];
    const float* bk = (const float*)d_in[4];
    const float* Wv = (const float*)d_in[5];
    const float* bv = (const float*)d_in[6];
    const float* Wo = (const float*)d_in[7];
    const float* bo = (const float*)d_in[8];
    const float* Wm1 = (const float*)d_in[9];
    const float* bm1 = (const float*)d_in[10];
    const float* Wm2 = (const float*)d_in[11];
    const float* bm2 = (const float*)d_in[12];
    const float* dop = (const float*)d_in[13];
    const float* ser = (const float*)d_in[14];
    const float* nor = (const float*)d_in[15];
    const float* ace = (const float*)d_in[16];
    const float* asc = (const float*)d_in[17];
    const float* abi = (const float*)d_in[18];
    float* out = (float*)d_out;

    float *q, *k, *v, *hid, *mod, *x;
    cudaGetSymbolAddress((void**)&q,   g_q);
    cudaGetSymbolAddress((void**)&k,   g_k);
    cudaGetSymbolAddress((void**)&v,   g_v);
    cudaGetSymbolAddress((void**)&hid, g_hid);
    cudaGetSymbolAddress((void**)&mod, g_mod);
    cudaGetSymbolAddress((void**)&x,   g_x);

    static int attrs_set = 0;
    if (!attrs_set) {
        cudaFuncSetAttribute(attn_mma_kernel,
            cudaFuncAttributeMaxDynamicSharedMemorySize, ATT_SMEM_BYTES);
        attrs_set = 1;
    }

    const int M = BB * SS;          // 4096
    dim3 blk(256);

    // Q, K, V projections (tf32 MMA; epilogue converts to tf32 bits,
    // Q pre-scaled by HD^-0.5)
    {
        dim3 grid(DD/128, M/128);
        gemm_mma_kernel<<<grid, blk>>>(query, Wq, bq, q, M, DD, DD, 0, 1, 0.125f);
        gemm_mma_kernel<<<grid, blk>>>(query, Wk, bk, k, M, DD, DD, 0, 1, 1.0f);
        gemm_mma_kernel<<<grid, blk>>>(query, Wv, bv, v, M, DD, DD, 0, 1, 1.0f);
    }

    // Attention (tf32 MMA flash, register softmax, cp.async pipeline)
    {
        dim3 grid(SS/128, BB*HH);
        attn_mma_kernel<<<grid, blk, ATT_SMEM_BYTES>>>();
    }

    // Neuromod MLP (tf32 MMA)
    {
        dim3 grid1(DM/128, M/128);
        gemm_mma_kernel<<<grid1, blk>>>(query, Wm1, bm1, hid, M, DM, DD, 1, 0, 0.f);
        dim3 grid2(DD/128, M/128);
        gemm_mma_kernel<<<grid2, blk>>>(hid, Wm2, bm2, mod, M, DD, DM, 0, 0, 0.f);
    }

    // Gate + merge heads
    {
        int n = BB*SS*DD;
        combine_kernel<<<(n + 255)/256, 256>>>(dop, ser, nor, ace, asc, abi);
    }

    // Output projection -> d_out (tf32 MMA)
    {
        dim3 grid(DD/128, M/128);
        gemm_mma_kernel<<<grid, blk>>>(x, Wo, bo, out, M, DD, DD, 0, 0, 0.f);
    }
}

// round 8
// speedup vs baseline: 3.4204x; 1.0369x over previous
#include <cuda_runtime.h>
#include <cstdint>
#include <cstddef>

// Problem constants
#define BB 2
#define SS 2048
#define DD 1024
#define HH 16
#define HDD 64
#define DM 256  // D/4

// Scratch (device globals — no runtime allocation allowed)
// g_q: tf32 bits pre-scaled by 0.125; g_k/g_v: tf32 bits; g_hid/g_x: tf32 bits.
__device__ float g_q[BB*HH*SS*HDD];
__device__ float g_k[BB*HH*SS*HDD];
__device__ float g_v[BB*HH*SS*HDD];
__device__ float g_attn[BB*HH*SS*HDD];
__device__ float g_hid[BB*SS*DM];
__device__ float g_mod[BB*SS*DD];
__device__ float g_x[BB*SS*DD];
// tf32-rounded operands (prepass)
__device__ float g_wq[DD*DD];
__device__ float g_wk[DD*DD];
__device__ float g_wv[DD*DD];
__device__ float g_wo[DD*DD];
__device__ float g_wm1[DM*DD];
__device__ float g_wm2[DD*DM];
__device__ float g_qr[BB*SS*DD];

// ===========================================================================
// Helpers (arch-agnostic PTX only: mma.sync tf32, cp.async — no tcgen05!)
// ===========================================================================
__device__ __forceinline__ uint32_t smem_u32(const void* p) {
    uint32_t a;
    asm("{ .reg .u64 t; cvta.to.shared.u64 t, %1; cvt.u32.u64 %0, t; }"
        : "=r"(a) : "l"(p));
    return a;
}

__device__ __forceinline__ uint32_t f2tf(float f) {
    uint32_t u;
    asm("cvt.rna.tf32.f32 %0, %1;" : "=r"(u) : "f"(f));
    return u;
}

// D += A @ B  (m16n8k8 tf32, A row-major, B col-major)
__device__ __forceinline__ void mma_tf32(float (&d)[4], const uint32_t (&a)[4],
                                         const uint32_t (&b)[2]) {
    asm volatile(
        "mma.sync.aligned.m16n8k8.row.col.f32.tf32.tf32.f32 "
        "{%0,%1,%2,%3}, {%4,%5,%6,%7}, {%8,%9}, {%0,%1,%2,%3};"
        : "+f"(d[0]), "+f"(d[1]), "+f"(d[2]), "+f"(d[3])
        : "r"(a[0]), "r"(a[1]), "r"(a[2]), "r"(a[3]), "r"(b[0]), "r"(b[1]));
}

__device__ __forceinline__ void cp16(uint32_t dst, const void* src) {
    asm volatile("cp.async.ca.shared.global [%0], [%1], 16;"
                 :: "r"(dst), "l"(src));
}
#define CP_COMMIT() asm volatile("cp.async.commit_group;" ::: "memory")
#define CP_WAIT1()  asm volatile("cp.async.wait_group 1;"  ::: "memory")
#define CP_WAIT0()  asm volatile("cp.async.wait_group 0;"  ::: "memory")

// ===========================================================================
// Prepass: round fp32 array to tf32 bits (RNA).
// ===========================================================================
__global__ void round_tf32_kernel(const float* __restrict__ src,
                                  float* __restrict__ dst, int n4)
{
    const int i = blockIdx.x * blockDim.x + threadIdx.x;
    if (i >= n4) return;
    float4 v = ((const float4*)src)[i];
    uint4 o = make_uint4(f2tf(v.x), f2tf(v.y), f2tf(v.z), f2tf(v.w));
    ((uint4*)dst)[i] = o;
}

// ===========================================================================
// tf32 MMA GEMM: C[M,N] = A[M,K] @ W[N,K]^T + bias[N]
// A and W must be PRE-ROUNDED tf32 bits. 128x128 CTA tile, 8 warps (32x64
// warp tile), BK=16 double-buffered cp.async, vectorized LDS.128 fragment
// loads via k-permutation (step h: slot tc <-> col 4tc+h, tc+4 <-> 4tc+2+h).
// relu: ReLU. split: head-split layout. conv != 0: store f2tf(val*conv) bits.
// ===========================================================================
__global__ void __launch_bounds__(256) gemm_mma_kernel(
    const float* __restrict__ A, const float* __restrict__ W,
    const float* __restrict__ bias, float* __restrict__ C,
    int M, int N, int K, int relu, int split, float conv)
{
    __shared__ float As[2][128*16];
    __shared__ float Bs[2][128*16];

    const int tid = threadIdx.x;
    const int wid = tid >> 5;
    const int lane = tid & 31;
    const int gr = lane >> 2;       // group row 0..7
    const int tc = lane & 3;        // thread col 0..3
    const int warp_m = wid & 3;     // 4 warps along M
    const int warp_n = wid >> 2;    // 2 warps along N
    const int m0 = blockIdx.y << 7;
    const int n0 = blockIdx.x << 7;

    const uint32_t sA[2] = { smem_u32(As[0]), smem_u32(As[1]) };
    const uint32_t sB[2] = { smem_u32(Bs[0]), smem_u32(Bs[1]) };

    float acc[2][8][4];
    #pragma unroll
    for (int mi = 0; mi < 2; mi++)
        #pragma unroll
        for (int nj = 0; nj < 8; nj++)
            #pragma unroll
            for (int q = 0; q < 4; q++) acc[mi][nj][q] = 0.f;

    const int KB = K >> 4;

    auto issue = [&](int kb, int buf) {
        #pragma unroll
        for (int i = 0; i < 2; i++) {
            const int ch = tid + (i << 8);       // 0..511
            const int row = ch >> 2, c4 = ch & 3;
            cp16(sA[buf] + (uint32_t)(row*16 + c4*4)*4,
                 A + (size_t)(m0 + row)*K + kb*16 + c4*4);
            cp16(sB[buf] + (uint32_t)(row*16 + c4*4)*4,
                 W + (size_t)(n0 + row)*K + kb*16 + c4*4);
        }
    };

    issue(0, 0);
    CP_COMMIT();

    for (int kb = 0; kb < KB; kb++) {
        const int buf = kb & 1;
        if (kb + 1 < KB) issue(kb + 1, buf ^ 1);
        CP_COMMIT();
        CP_WAIT1();
        __syncthreads();

        const uint32_t* a_s = (const uint32_t*)As[buf];
        const uint32_t* b_s = (const uint32_t*)Bs[buf];

        // A fragments: both k-steps from one uint4 per row-half
        uint4 a4[2][2];
        #pragma unroll
        for (int mi = 0; mi < 2; mi++) {
            const int r = warp_m*32 + mi*16 + gr;
            a4[mi][0] = *(const uint4*)(a_s + r*16 + 4*tc);
            a4[mi][1] = *(const uint4*)(a_s + (r+8)*16 + 4*tc);
        }
        uint32_t af0[2][4], af1[2][4];
        #pragma unroll
        for (int mi = 0; mi < 2; mi++) {
            af0[mi][0] = a4[mi][0].x; af0[mi][1] = a4[mi][1].x;
            af0[mi][2] = a4[mi][0].z; af0[mi][3] = a4[mi][1].z;
            af1[mi][0] = a4[mi][0].y; af1[mi][1] = a4[mi][1].y;
            af1[mi][2] = a4[mi][0].w; af1[mi][3] = a4[mi][1].w;
        }
        #pragma unroll
        for (int nj = 0; nj < 8; nj++) {
            const int n = warp_n*64 + nj*8 + gr;
            uint4 b4 = *(const uint4*)(b_s + n*16 + 4*tc);
            uint32_t bf0[2] = { b4.x, b4.z };
            uint32_t bf1[2] = { b4.y, b4.w };
            mma_tf32(acc[0][nj], af0[0], bf0);
            mma_tf32(acc[1][nj], af0[1], bf0);
            mma_tf32(acc[0][nj], af1[0], bf1);
            mma_tf32(acc[1][nj], af1[1], bf1);
        }
        __syncthreads();
    }

    // Epilogue
    #pragma unroll
    for (int mi = 0; mi < 2; mi++) {
        const int row = m0 + warp_m*32 + mi*16 + gr;
        #pragma unroll
        for (int nj = 0; nj < 8; nj++) {
            const int col = n0 + warp_n*64 + nj*8 + 2*tc;
            const float b0 = bias[col], b1 = bias[col+1];
            float2 v0 = make_float2(acc[mi][nj][0] + b0, acc[mi][nj][1] + b1);
            float2 v1 = make_float2(acc[mi][nj][2] + b0, acc[mi][nj][3] + b1);
            if (relu) {
                v0.x = fmaxf(v0.x, 0.f); v0.y = fmaxf(v0.y, 0.f);
                v1.x = fmaxf(v1.x, 0.f); v1.y = fmaxf(v1.y, 0.f);
            }
            if (conv != 0.f) {   // store tf32 bits (optionally pre-scaled)
                v0.x = __uint_as_float(f2tf(v0.x * conv));
                v0.y = __uint_as_float(f2tf(v0.y * conv));
                v1.x = __uint_as_float(f2tf(v1.x * conv));
                v1.y = __uint_as_float(f2tf(v1.y * conv));
            }
            if (split) {
                const int b = row >> 11, s = row & (SS - 1);
                const int h = col >> 6, hd = col & 63;
                float* d0 = C + (((size_t)(b*HH + h))*SS + s)*HDD + hd;
                const int rb = (row+8) >> 11, rs = (row+8) & (SS - 1);
                float* d1 = C + (((size_t)(rb*HH + h))*SS + rs)*HDD + hd;
                *(float2*)d0 = v0;
                *(float2*)d1 = v1;
            } else {
                *(float2*)(C + (size_t)row*N + col) = v0;
                *(float2*)(C + (size_t)(row+8)*N + col) = v1;
            }
        }
    }
}

// ===========================================================================
// Flash attention, tf32 MMA, P fully register-resident (no P smem!),
// vectorized K fragment loads, cp.async double buffer, 1 sync per tile.
//
// S-MMA (k = hd, permuted): step s=2g+h uses hd cols slot tc -> 16g+4tc+h,
//   slot tc+4 -> 16g+4tc+2+h. Q regs loaded to match; K rows give B frags
//   via one uint4 per (nj,g).
// PV-MMA (k = keys, permuted): step nj uses keys slot tc -> nj*8+2tc,
//   slot tc+4 -> nj*8+2tc+1, which makes the S accumulator fragment layout
//   a legal A fragment: pa = {e0, e2, e1, e3} of exp'd sacc[nj].
// smem: Kd[2][64*80]  Vd[2][64*68]  (strides chosen conflict-free)
// ===========================================================================
#define KP 80
#define VP 68
#define KTILE (64*KP)
#define VTILE (64*VP)
#define ATT_SMEM_BYTES ((2*KTILE + 2*VTILE)*4)

__global__ void __launch_bounds__(256, 2) attn_mma_kernel()
{
    extern __shared__ float sm[];
    float* Kd = sm;                 // [2][64*KP] tf32 bits
    float* Vd = sm + 2*KTILE;       // [2][64*VP] tf32 bits

    const int tid = threadIdx.x;
    const int wid = tid >> 5;
    const int lane = tid & 31;
    const int gr = lane >> 2;
    const int tc = lane & 3;

    const int bh = blockIdx.y;
    const int m0 = blockIdx.x << 7;
    const float* Qg = g_q + (size_t)bh * SS * HDD;
    const float* Kg = g_k + (size_t)bh * SS * HDD;
    const float* Vg = g_v + (size_t)bh * SS * HDD;
    float*       Og = g_attn + (size_t)bh * SS * HDD;

    const uint32_t sK = smem_u32(Kd);
    const uint32_t sV = smem_u32(Vd);

    auto issue_kv = [&](int kt, int buf) {
        const int kbase = kt << 6;
        #pragma unroll
        for (int i = 0; i < 4; i++) {
            const int ch = tid + (i << 8);          // 0..1023
            const int row = ch >> 4, c16 = ch & 15;
            const size_t soff = (size_t)(kbase + row)*HDD + c16*4;
            cp16(sK + (uint32_t)(buf*KTILE + row*KP + c16*4)*4, Kg + soff);
            cp16(sV + (uint32_t)(buf*VTILE + row*VP + c16*4)*4, Vg + soff);
        }
    };

    // Q fragments (tf32 bits, pre-scaled), permuted hd mapping
    uint32_t qa[8][4];
    {
        const uint32_t* q0 = (const uint32_t*)(Qg + (size_t)(m0 + wid*16 + gr) * HDD);
        const uint32_t* q1 = q0 + 8 * HDD;
        #pragma unroll
        for (int g = 0; g < 4; g++) {
            uint4 ua = *(const uint4*)(q0 + 16*g + 4*tc);
            uint4 ub = *(const uint4*)(q1 + 16*g + 4*tc);
            qa[2*g][0]   = ua.x; qa[2*g+1][0] = ua.y;
            qa[2*g][2]   = ua.z; qa[2*g+1][2] = ua.w;
            qa[2*g][1]   = ub.x; qa[2*g+1][1] = ub.y;
            qa[2*g][3]   = ub.z; qa[2*g+1][3] = ub.w;
        }
    }

    float m0s = -1e30f, m1s = -1e30f, l0s = 0.f, l1s = 0.f;
    float o[8][4];
    #pragma unroll
    for (int nj = 0; nj < 8; nj++)
        #pragma unroll
        for (int q = 0; q < 4; q++) o[nj][q] = 0.f;

    issue_kv(0, 0);
    CP_COMMIT();

    const int NT = SS / 64;
    for (int kt = 0; kt < NT; kt++) {
        const int buf = kt & 1;
        CP_WAIT0();
        __syncthreads();
        if (kt + 1 < NT) { issue_kv(kt + 1, buf ^ 1); CP_COMMIT(); }

        const float* Ks = Kd + buf*KTILE;
        const float* Vs = Vd + buf*VTILE;

        // S = Q @ K^T (warp: 16 rows x 64 keys), vectorized B loads
        float sacc[8][4];
        #pragma unroll
        for (int nj = 0; nj < 8; nj++)
            #pragma unroll
            for (int q = 0; q < 4; q++) sacc[nj][q] = 0.f;
        #pragma unroll
        for (int nj = 0; nj < 8; nj++) {
            const uint32_t* krow = (const uint32_t*)(Ks + (nj*8 + gr)*KP);
            #pragma unroll
            for (int g = 0; g < 4; g++) {
                uint4 kb = *(const uint4*)(krow + 16*g + 4*tc);
                uint32_t bf0[2] = { kb.x, kb.z };
                uint32_t bf1[2] = { kb.y, kb.w };
                mma_tf32(sacc[nj], qa[2*g],   bf0);
                mma_tf32(sacc[nj], qa[2*g+1], bf1);
            }
        }

        // Register online softmax (rows gr -> elems 0,1; gr+8 -> 2,3)
        float mx0 = -1e30f, mx1 = -1e30f;
        #pragma unroll
        for (int nj = 0; nj < 8; nj++) {
            mx0 = fmaxf(mx0, fmaxf(sacc[nj][0], sacc[nj][1]));
            mx1 = fmaxf(mx1, fmaxf(sacc[nj][2], sacc[nj][3]));
        }
        mx0 = fmaxf(mx0, __shfl_xor_sync(0xffffffffu, mx0, 1));
        mx0 = fmaxf(mx0, __shfl_xor_sync(0xffffffffu, mx0, 2));
        mx1 = fmaxf(mx1, __shfl_xor_sync(0xffffffffu, mx1, 1));
        mx1 = fmaxf(mx1, __shfl_xor_sync(0xffffffffu, mx1, 2));

        const float mn0 = fmaxf(m0s, mx0);
        const float mn1 = fmaxf(m1s, mx1);
        const float c0 = __expf(m0s - mn0);
        const float c1 = __expf(m1s - mn1);
        float s0 = 0.f, s1 = 0.f;

        // exp in place; sacc becomes tf32 P bits
        #pragma unroll
        for (int nj = 0; nj < 8; nj++) {
            const float p00 = __expf(sacc[nj][0] - mn0);
            const float p01 = __expf(sacc[nj][1] - mn0);
            const float p10 = __expf(sacc[nj][2] - mn1);
            const float p11 = __expf(sacc[nj][3] - mn1);
            s0 += p00 + p01;
            s1 += p10 + p11;
            sacc[nj][0] = __uint_as_float(f2tf(p00));
            sacc[nj][1] = __uint_as_float(f2tf(p01));
            sacc[nj][2] = __uint_as_float(f2tf(p10));
            sacc[nj][3] = __uint_as_float(f2tf(p11));
        }
        s0 += __shfl_xor_sync(0xffffffffu, s0, 1);
        s0 += __shfl_xor_sync(0xffffffffu, s0, 2);
        s1 += __shfl_xor_sync(0xffffffffu, s1, 1);
        s1 += __shfl_xor_sync(0xffffffffu, s1, 2);
        l0s = l0s*c0 + s0;  m0s = mn0;
        l1s = l1s*c1 + s1;  m1s = mn1;

        // Rescale O
        #pragma unroll
        for (int nj = 0; nj < 8; nj++) {
            o[nj][0] *= c0; o[nj][1] *= c0;
            o[nj][2] *= c1; o[nj][3] *= c1;
        }

        // O += P @ V  — P from registers (permuted key slots)
        #pragma unroll
        for (int nj = 0; nj < 8; nj++) {
            uint32_t pa[4] = { __float_as_uint(sacc[nj][0]),
                               __float_as_uint(sacc[nj][2]),
                               __float_as_uint(sacc[nj][1]),
                               __float_as_uint(sacc[nj][3]) };
            const uint32_t* v0 = (const uint32_t*)(Vs + (nj*8 + 2*tc)*VP);
            const uint32_t* v1 = v0 + VP;
            #pragma unroll
            for (int njo = 0; njo < 8; njo++) {
                uint32_t vb[2] = { v0[njo*8 + gr], v1[njo*8 + gr] };
                mma_tf32(o[njo], pa, vb);
            }
        }
    }

    // Normalize and write
    {
        const int row0 = wid*16 + gr;
        const float inv0 = 1.f / l0s;
        const float inv1 = 1.f / l1s;
        #pragma unroll
        for (int nj = 0; nj < 8; nj++) {
            const int col = nj*8 + 2*tc;
            *(float2*)(Og + (size_t)(m0 + row0)*HDD + col) =
                make_float2(o[nj][0]*inv0, o[nj][1]*inv0);
            *(float2*)(Og + (size_t)(m0 + row0 + 8)*HDD + col) =
                make_float2(o[nj][2]*inv1, o[nj][3]*inv1);
        }
    }
}

// ---------------------------------------------------------------------------
// Combine: x[b,s,d] = (attn*scale + bias) * (1 + mod*gate), head-merge,
// emitted as tf32 bits (consumed by Wo GEMM).
// ---------------------------------------------------------------------------
__global__ void combine_kernel(const float* __restrict__ dop,
                               const float* __restrict__ ser,
                               const float* __restrict__ nor,
                               const float* __restrict__ ace,
                               const float* __restrict__ asc,
                               const float* __restrict__ abi)
{
    const int idx = blockIdx.x * blockDim.x + threadIdx.x;
    if (idx >= BB*SS*DD) return;
    const float gate = 0.25f * (dop[0] + ser[0] + nor[0] + ace[0]);
    const int d = idx & (DD - 1);
    const int s = (idx >> 10) & (SS - 1);
    const int b = idx >> 21;
    const int h = d >> 6, hd = d & 63;
    const float a = g_attn[(((size_t)(b*HH + h))*SS + s)*HDD + hd];
    const float mo = g_mod[idx];
    const float val = (a * asc[0] + abi[0]) * (1.f + mo * gate);
    g_x[idx] = __uint_as_float(f2tf(val));
}

// ---------------------------------------------------------------------------
extern "C" void kernel_launch(void* const* d_in, const int* in_sizes, int n_in,
                              void* d_out, int out_size)
{
    const float* query = (const float*)d_in[0];
    const float* Wq = (const float*)d_in[1];
    const float* bq = (const float*)d_in[2];
    const float* Wk = (const float*)d_in[3];
    const float* bk = (const float*)d_in[4];
    const float* Wv = (const float*)d_in[5];
    const float* bv = (const float*)d_in[6];
    const float* Wo = (const float*)d_in[7];
    const float* bo = (const float*)d_in[8];
    const float* Wm1 = (const float*)d_in[9];
    const float* bm1 = (const float*)d_in[10];
    const float* Wm2 = (const float*)d_in[11];
    const float* bm2 = (const float*)d_in[12];
    const float* dop = (const float*)d_in[13];
    const float* ser = (const float*)d_in[14];
    const float* nor = (const float*)d_in[15];
    const float* ace = (const float*)d_in[16];
    const float* asc = (const float*)d_in[17];
    const float* abi = (const float*)d_in[18];
    float* out = (float*)d_out;

    float *q, *k, *v, *hid, *mod, *x;
    float *wq, *wk, *wv, *wo, *wm1, *wm2, *qr;
    cudaGetSymbolAddress((void**)&q,   g_q);
    cudaGetSymbolAddress((void**)&k,   g_k);
    cudaGetSymbolAddress((void**)&v,   g_v);
    cudaGetSymbolAddress((void**)&hid, g_hid);
    cudaGetSymbolAddress((void**)&mod, g_mod);
    cudaGetSymbolAddress((void**)&x,   g_x);
    cudaGetSymbolAddress((void**)&wq,  g_wq);
    cudaGetSymbolAddress((void**)&wk,  g_wk);
    cudaGetSymbolAddress((void**)&wv,  g_wv);
    cudaGetSymbolAddress((void**)&wo,  g_wo);
    cudaGetSymbolAddress((void**)&wm1, g_wm1);
    cudaGetSymbolAddress((void**)&wm2, g_wm2);
    cudaGetSymbolAddress((void**)&qr,  g_qr);

    static int attrs_set = 0;
    if (!attrs_set) {
        cudaFuncSetAttribute(attn_mma_kernel,
            cudaFuncAttributeMaxDynamicSharedMemorySize, ATT_SMEM_BYTES);
        attrs_set = 1;
    }

    const int M = BB * SS;          // 4096
    dim3 blk(256);

    // Prepass: round all GEMM operands to tf32 once
    {
        round_tf32_kernel<<<(DD*DD/4 + 255)/256, 256>>>(Wq,  wq,  DD*DD/4);
        round_tf32_kernel<<<(DD*DD/4 + 255)/256, 256>>>(Wk,  wk,  DD*DD/4);
        round_tf32_kernel<<<(DD*DD/4 + 255)/256, 256>>>(Wv,  wv,  DD*DD/4);
        round_tf32_kernel<<<(DD*DD/4 + 255)/256, 256>>>(Wo,  wo,  DD*DD/4);
        round_tf32_kernel<<<(DM*DD/4 + 255)/256, 256>>>(Wm1, wm1, DM*DD/4);
        round_tf32_kernel<<<(DD*DM/4 + 255)/256, 256>>>(Wm2, wm2, DD*DM/4);
        round_tf32_kernel<<<(M*DD/4  + 255)/256, 256>>>(query, qr, M*DD/4);
    }

    // Q, K, V projections (epilogue emits tf32 bits; Q pre-scaled by HD^-0.5)
    {
        dim3 grid(DD/128, M/128);
        gemm_mma_kernel<<<grid, blk>>>(qr, wq, bq, q, M, DD, DD, 0, 1, 0.125f);
        gemm_mma_kernel<<<grid, blk>>>(qr, wk, bk, k, M, DD, DD, 0, 1, 1.0f);
        gemm_mma_kernel<<<grid, blk>>>(qr, wv, bv, v, M, DD, DD, 0, 1, 1.0f);
    }

    // Attention
    {
        dim3 grid(SS/128, BB*HH);
        attn_mma_kernel<<<grid, blk, ATT_SMEM_BYTES>>>();
    }

    // Neuromod MLP (hid emitted as tf32 bits for second GEMM)
    {
        dim3 grid1(DM/128, M/128);
        gemm_mma_kernel<<<grid1, blk>>>(qr, wm1, bm1, hid, M, DM, DD, 1, 0, 1.0f);
        dim3 grid2(DD/128, M/128);
        gemm_mma_kernel<<<grid2, blk>>>(hid, wm2, bm2, mod, M, DD, DM, 0, 0, 0.f);
    }

    // Gate + merge heads (emits tf32 bits into g_x)
    {
        int n = BB*SS*DD;
        combine_kernel<<<(n + 255)/256, 256>>>(dop, ser, nor, ace, asc, abi);
    }

    // Output projection -> d_out (fp32 out)
    {
        dim3 grid(DD/128, M/128);
        gemm_mma_kernel<<<grid, blk>>>(x, wo, bo, out, M, DD, DD, 0, 0, 0.f);
    }
}

// round 9
// speedup vs baseline: 3.5456x; 1.0366x over previous
#include <cuda_runtime.h>
#include <cstdint>
#include <cstddef>

// Problem constants
#define BB 2
#define SS 2048
#define DD 1024
#define HH 16
#define HDD 64
#define DM 256  // D/4

// Scratch (device globals — no runtime allocation allowed)
// g_q: tf32 bits pre-scaled by 0.125; g_k/g_v: tf32 bits; g_hid/g_x: tf32 bits.
__device__ float g_q[BB*HH*SS*HDD];
__device__ float g_k[BB*HH*SS*HDD];
__device__ float g_v[BB*HH*SS*HDD];
__device__ float g_attn[BB*HH*SS*HDD];
__device__ float g_hid[BB*SS*DM];
__device__ float g_x[BB*SS*DD];
// tf32-rounded operands (prepass)
__device__ float g_wq[DD*DD];
__device__ float g_wk[DD*DD];
__device__ float g_wv[DD*DD];
__device__ float g_wo[DD*DD];
__device__ float g_wm1[DM*DD];
__device__ float g_wm2[DD*DM];
__device__ float g_qr[BB*SS*DD];

// ===========================================================================
// Helpers (arch-agnostic PTX only: mma.sync tf32, cp.async — no tcgen05!)
// ===========================================================================
__device__ __forceinline__ uint32_t smem_u32(const void* p) {
    uint32_t a;
    asm("{ .reg .u64 t; cvta.to.shared.u64 t, %1; cvt.u32.u64 %0, t; }"
        : "=r"(a) : "l"(p));
    return a;
}

__device__ __forceinline__ uint32_t f2tf(float f) {
    uint32_t u;
    asm("cvt.rna.tf32.f32 %0, %1;" : "=r"(u) : "f"(f));
    return u;
}

// D += A @ B  (m16n8k8 tf32, A row-major, B col-major)
__device__ __forceinline__ void mma_tf32(float (&d)[4], const uint32_t (&a)[4],
                                         const uint32_t (&b)[2]) {
    asm volatile(
        "mma.sync.aligned.m16n8k8.row.col.f32.tf32.tf32.f32 "
        "{%0,%1,%2,%3}, {%4,%5,%6,%7}, {%8,%9}, {%0,%1,%2,%3};"
        : "+f"(d[0]), "+f"(d[1]), "+f"(d[2]), "+f"(d[3])
        : "r"(a[0]), "r"(a[1]), "r"(a[2]), "r"(a[3]), "r"(b[0]), "r"(b[1]));
}

__device__ __forceinline__ void cp16(uint32_t dst, const void* src) {
    asm volatile("cp.async.ca.shared.global [%0], [%1], 16;"
                 :: "r"(dst), "l"(src));
}
#define CP_COMMIT() asm volatile("cp.async.commit_group;" ::: "memory")
#define CP_WAIT1()  asm volatile("cp.async.wait_group 1;"  ::: "memory")
#define CP_WAIT0()  asm volatile("cp.async.wait_group 0;"  ::: "memory")

// ===========================================================================
// Prepass: round 7 fp32 arrays to tf32 bits (RNA) in ONE launch.
// Segments (uint4 units): wq,wk,wv,wo (256K each), wm1,wm2 (64K), qr (1M).
// ===========================================================================
#define SEG_W  (DD*DD/4)     // 262144
#define SEG_M  (DM*DD/4)     // 65536
#define SEG_Q  (BB*SS*DD/4)  // 1048576
#define SEG_TOT (4*SEG_W + 2*SEG_M + SEG_Q)

__global__ void round_all_kernel(
    const float* __restrict__ s0, const float* __restrict__ s1,
    const float* __restrict__ s2, const float* __restrict__ s3,
    const float* __restrict__ s4, const float* __restrict__ s5,
    const float* __restrict__ s6,
    float* __restrict__ d0, float* __restrict__ d1,
    float* __restrict__ d2, float* __restrict__ d3,
    float* __restrict__ d4, float* __restrict__ d5,
    float* __restrict__ d6)
{
    int i = blockIdx.x * blockDim.x + threadIdx.x;
    if (i >= SEG_TOT) return;
    const float* src; float* dst;
    if      (i < SEG_W)              { src = s0; dst = d0; }
    else if (i < 2*SEG_W)            { src = s1; dst = d1; i -= SEG_W; }
    else if (i < 3*SEG_W)            { src = s2; dst = d2; i -= 2*SEG_W; }
    else if (i < 4*SEG_W)            { src = s3; dst = d3; i -= 3*SEG_W; }
    else if (i < 4*SEG_W + SEG_M)    { src = s4; dst = d4; i -= 4*SEG_W; }
    else if (i < 4*SEG_W + 2*SEG_M)  { src = s5; dst = d5; i -= 4*SEG_W + SEG_M; }
    else                             { src = s6; dst = d6; i -= 4*SEG_W + 2*SEG_M; }
    float4 v = ((const float4*)src)[i];
    ((uint4*)dst)[i] = make_uint4(f2tf(v.x), f2tf(v.y), f2tf(v.z), f2tf(v.w));
}

// ===========================================================================
// tf32 MMA GEMM: C[M,N] = A[M,K] @ W[N,K]^T + bias[N]
// A and W PRE-ROUNDED tf32 bits. 128x128 CTA tile, 8 warps (32x64 warp tile),
// BK=32 double-buffered cp.async (dynamic smem 64KB, 2 CTAs/SM), vectorized
// LDS.128 fragment loads via k-permutation.
// relu: ReLU. split: head-split layout. conv != 0: store f2tf(val*conv).
// gate: epilogue x = (attn*asc + abi)*(1 + mod*gate4) -> tf32 bits (C=g_x).
// ===========================================================================
#define GBK 32
#define GTILE (128*GBK)
#define GEMM_SMEM_BYTES (4*GTILE*4)   // As[2] + Bs[2]

__global__ void __launch_bounds__(256, 2) gemm_mma_kernel(
    const float* __restrict__ A, const float* __restrict__ W,
    const float* __restrict__ bias, float* __restrict__ C,
    int M, int N, int K, int relu, int split, float conv, int gate,
    const float* __restrict__ dop, const float* __restrict__ ser,
    const float* __restrict__ nor, const float* __restrict__ ace,
    const float* __restrict__ asc, const float* __restrict__ abi)
{
    extern __shared__ float gsm[];
    float* As0 = gsm;
    float* As1 = gsm + GTILE;
    float* Bs0 = gsm + 2*GTILE;
    float* Bs1 = gsm + 3*GTILE;

    const int tid = threadIdx.x;
    const int wid = tid >> 5;
    const int lane = tid & 31;
    const int gr = lane >> 2;       // group row 0..7
    const int tc = lane & 3;        // thread col 0..3
    const int warp_m = wid & 3;     // 4 warps along M
    const int warp_n = wid >> 2;    // 2 warps along N
    const int m0 = blockIdx.y << 7;
    const int n0 = blockIdx.x << 7;

    const uint32_t sA[2] = { smem_u32(As0), smem_u32(As1) };
    const uint32_t sB[2] = { smem_u32(Bs0), smem_u32(Bs1) };
    const float* Abuf[2] = { As0, As1 };
    const float* Bbuf[2] = { Bs0, Bs1 };

    float acc[2][8][4];
    #pragma unroll
    for (int mi = 0; mi < 2; mi++)
        #pragma unroll
        for (int nj = 0; nj < 8; nj++)
            #pragma unroll
            for (int q = 0; q < 4; q++) acc[mi][nj][q] = 0.f;

    const int KB = K >> 5;

    // 128 rows x 32 floats per matrix = 1024 cp16 -> 4 per thread per matrix
    auto issue = [&](int kb, int buf) {
        #pragma unroll
        for (int i = 0; i < 4; i++) {
            const int ch = tid + (i << 8);       // 0..1023
            const int row = ch >> 3, c8 = ch & 7;
            cp16(sA[buf] + (uint32_t)(row*GBK + c8*4)*4,
                 A + (size_t)(m0 + row)*K + kb*GBK + c8*4);
            cp16(sB[buf] + (uint32_t)(row*GBK + c8*4)*4,
                 W + (size_t)(n0 + row)*K + kb*GBK + c8*4);
        }
    };

    issue(0, 0);
    CP_COMMIT();

    for (int kb = 0; kb < KB; kb++) {
        const int buf = kb & 1;
        if (kb + 1 < KB) issue(kb + 1, buf ^ 1);
        CP_COMMIT();
        CP_WAIT1();
        __syncthreads();

        const uint32_t* a_s = (const uint32_t*)Abuf[buf];
        const uint32_t* b_s = (const uint32_t*)Bbuf[buf];

        #pragma unroll
        for (int ks = 0; ks < GBK; ks += 16) {
            uint4 a4[2][2];
            #pragma unroll
            for (int mi = 0; mi < 2; mi++) {
                const int r = warp_m*32 + mi*16 + gr;
                a4[mi][0] = *(const uint4*)(a_s + r*GBK + ks + 4*tc);
                a4[mi][1] = *(const uint4*)(a_s + (r+8)*GBK + ks + 4*tc);
            }
            uint32_t af0[2][4], af1[2][4];
            #pragma unroll
            for (int mi = 0; mi < 2; mi++) {
                af0[mi][0] = a4[mi][0].x; af0[mi][1] = a4[mi][1].x;
                af0[mi][2] = a4[mi][0].z; af0[mi][3] = a4[mi][1].z;
                af1[mi][0] = a4[mi][0].y; af1[mi][1] = a4[mi][1].y;
                af1[mi][2] = a4[mi][0].w; af1[mi][3] = a4[mi][1].w;
            }
            #pragma unroll
            for (int nj = 0; nj < 8; nj++) {
                const int n = warp_n*64 + nj*8 + gr;
                uint4 b4 = *(const uint4*)(b_s + n*GBK + ks + 4*tc);
                uint32_t bf0[2] = { b4.x, b4.z };
                uint32_t bf1[2] = { b4.y, b4.w };
                mma_tf32(acc[0][nj], af0[0], bf0);
                mma_tf32(acc[1][nj], af0[1], bf0);
                mma_tf32(acc[0][nj], af1[0], bf1);
                mma_tf32(acc[1][nj], af1[1], bf1);
            }
        }
        __syncthreads();
    }

    // Epilogue
    float gate4 = 0.f, ascv = 0.f, abiv = 0.f;
    if (gate) {
        gate4 = 0.25f * (dop[0] + ser[0] + nor[0] + ace[0]);
        ascv = asc[0];
        abiv = abi[0];
    }
    #pragma unroll
    for (int mi = 0; mi < 2; mi++) {
        const int row = m0 + warp_m*32 + mi*16 + gr;
        #pragma unroll
        for (int nj = 0; nj < 8; nj++) {
            const int col = n0 + warp_n*64 + nj*8 + 2*tc;
            const float b0 = bias[col], b1 = bias[col+1];
            float2 v0 = make_float2(acc[mi][nj][0] + b0, acc[mi][nj][1] + b1);
            float2 v1 = make_float2(acc[mi][nj][2] + b0, acc[mi][nj][3] + b1);
            if (relu) {
                v0.x = fmaxf(v0.x, 0.f); v0.y = fmaxf(v0.y, 0.f);
                v1.x = fmaxf(v1.x, 0.f); v1.y = fmaxf(v1.y, 0.f);
            }
            if (gate) {
                // mod -> x = (attn*asc + abi) * (1 + mod*gate4), tf32 bits
                const int b = row >> 11, s = row & (SS - 1);
                const int h = col >> 6, hd = col & 63;
                const int rb = (row+8) >> 11, rs = (row+8) & (SS - 1);
                float2 a0 = *(const float2*)(g_attn +
                    (((size_t)(b*HH + h))*SS + s)*HDD + hd);
                float2 a1 = *(const float2*)(g_attn +
                    (((size_t)(rb*HH + h))*SS + rs)*HDD + hd);
                v0.x = __uint_as_float(f2tf((a0.x*ascv + abiv)*(1.f + v0.x*gate4)));
                v0.y = __uint_as_float(f2tf((a0.y*ascv + abiv)*(1.f + v0.y*gate4)));
                v1.x = __uint_as_float(f2tf((a1.x*ascv + abiv)*(1.f + v1.x*gate4)));
                v1.y = __uint_as_float(f2tf((a1.y*ascv + abiv)*(1.f + v1.y*gate4)));
            } else if (conv != 0.f) {
                v0.x = __uint_as_float(f2tf(v0.x * conv));
                v0.y = __uint_as_float(f2tf(v0.y * conv));
                v1.x = __uint_as_float(f2tf(v1.x * conv));
                v1.y = __uint_as_float(f2tf(v1.y * conv));
            }
            if (split) {
                const int b = row >> 11, s = row & (SS - 1);
                const int h = col >> 6, hd = col & 63;
                float* d0 = C + (((size_t)(b*HH + h))*SS + s)*HDD + hd;
                const int rb = (row+8) >> 11, rs = (row+8) & (SS - 1);
                float* d1 = C + (((size_t)(rb*HH + h))*SS + rs)*HDD + hd;
                *(float2*)d0 = v0;
                *(float2*)d1 = v1;
            } else {
                *(float2*)(C + (size_t)row*N + col) = v0;
                *(float2*)(C + (size_t)(row+8)*N + col) = v1;
            }
        }
    }
}

// ===========================================================================
// Flash attention, tf32 MMA, P fully register-resident (no P smem),
// vectorized K fragment loads, cp.async double buffer, 1 sync per tile.
// smem: Kd[2][64*80]  Vd[2][64*68]  (strides conflict-free)
// ===========================================================================
#define KP 80
#define VP 68
#define KTILE (64*KP)
#define VTILE (64*VP)
#define ATT_SMEM_BYTES ((2*KTILE + 2*VTILE)*4)

__global__ void __launch_bounds__(256, 2) attn_mma_kernel()
{
    extern __shared__ float sm[];
    float* Kd = sm;                 // [2][64*KP] tf32 bits
    float* Vd = sm + 2*KTILE;       // [2][64*VP] tf32 bits

    const int tid = threadIdx.x;
    const int wid = tid >> 5;
    const int lane = tid & 31;
    const int gr = lane >> 2;
    const int tc = lane & 3;

    const int bh = blockIdx.y;
    const int m0 = blockIdx.x << 7;
    const float* Qg = g_q + (size_t)bh * SS * HDD;
    const float* Kg = g_k + (size_t)bh * SS * HDD;
    const float* Vg = g_v + (size_t)bh * SS * HDD;
    float*       Og = g_attn + (size_t)bh * SS * HDD;

    const uint32_t sK = smem_u32(Kd);
    const uint32_t sV = smem_u32(Vd);

    auto issue_kv = [&](int kt, int buf) {
        const int kbase = kt << 6;
        #pragma unroll
        for (int i = 0; i < 4; i++) {
            const int ch = tid + (i << 8);          // 0..1023
            const int row = ch >> 4, c16 = ch & 15;
            const size_t soff = (size_t)(kbase + row)*HDD + c16*4;
            cp16(sK + (uint32_t)(buf*KTILE + row*KP + c16*4)*4, Kg + soff);
            cp16(sV + (uint32_t)(buf*VTILE + row*VP + c16*4)*4, Vg + soff);
        }
    };

    // Q fragments (tf32 bits, pre-scaled), permuted hd mapping
    uint32_t qa[8][4];
    {
        const uint32_t* q0 = (const uint32_t*)(Qg + (size_t)(m0 + wid*16 + gr) * HDD);
        const uint32_t* q1 = q0 + 8 * HDD;
        #pragma unroll
        for (int g = 0; g < 4; g++) {
            uint4 ua = *(const uint4*)(q0 + 16*g + 4*tc);
            uint4 ub = *(const uint4*)(q1 + 16*g + 4*tc);
            qa[2*g][0]   = ua.x; qa[2*g+1][0] = ua.y;
            qa[2*g][2]   = ua.z; qa[2*g+1][2] = ua.w;
            qa[2*g][1]   = ub.x; qa[2*g+1][1] = ub.y;
            qa[2*g][3]   = ub.z; qa[2*g+1][3] = ub.w;
        }
    }

    float m0s = -1e30f, m1s = -1e30f, l0s = 0.f, l1s = 0.f;
    float o[8][4];
    #pragma unroll
    for (int nj = 0; nj < 8; nj++)
        #pragma unroll
        for (int q = 0; q < 4; q++) o[nj][q] = 0.f;

    issue_kv(0, 0);
    CP_COMMIT();

    const int NT = SS / 64;
    for (int kt = 0; kt < NT; kt++) {
        const int buf = kt & 1;
        CP_WAIT0();
        __syncthreads();
        if (kt + 1 < NT) { issue_kv(kt + 1, buf ^ 1); CP_COMMIT(); }

        const float* Ks = Kd + buf*KTILE;
        const float* Vs = Vd + buf*VTILE;

        // S = Q @ K^T (warp: 16 rows x 64 keys), vectorized B loads
        float sacc[8][4];
        #pragma unroll
        for (int nj = 0; nj < 8; nj++)
            #pragma unroll
            for (int q = 0; q < 4; q++) sacc[nj][q] = 0.f;
        #pragma unroll
        for (int nj = 0; nj < 8; nj++) {
            const uint32_t* krow = (const uint32_t*)(Ks + (nj*8 + gr)*KP);
            #pragma unroll
            for (int g = 0; g < 4; g++) {
                uint4 kb = *(const uint4*)(krow + 16*g + 4*tc);
                uint32_t bf0[2] = { kb.x, kb.z };
                uint32_t bf1[2] = { kb.y, kb.w };
                mma_tf32(sacc[nj], qa[2*g],   bf0);
                mma_tf32(sacc[nj], qa[2*g+1], bf1);
            }
        }

        // Register online softmax (rows gr -> elems 0,1; gr+8 -> 2,3)
        float mx0 = -1e30f, mx1 = -1e30f;
        #pragma unroll
        for (int nj = 0; nj < 8; nj++) {
            mx0 = fmaxf(mx0, fmaxf(sacc[nj][0], sacc[nj][1]));
            mx1 = fmaxf(mx1, fmaxf(sacc[nj][2], sacc[nj][3]));
        }
        mx0 = fmaxf(mx0, __shfl_xor_sync(0xffffffffu, mx0, 1));
        mx0 = fmaxf(mx0, __shfl_xor_sync(0xffffffffu, mx0, 2));
        mx1 = fmaxf(mx1, __shfl_xor_sync(0xffffffffu, mx1, 1));
        mx1 = fmaxf(mx1, __shfl_xor_sync(0xffffffffu, mx1, 2));

        const float mn0 = fmaxf(m0s, mx0);
        const float mn1 = fmaxf(m1s, mx1);
        const float c0 = __expf(m0s - mn0);
        const float c1 = __expf(m1s - mn1);
        float s0 = 0.f, s1 = 0.f;

        #pragma unroll
        for (int nj = 0; nj < 8; nj++) {
            const float p00 = __expf(sacc[nj][0] - mn0);
            const float p01 = __expf(sacc[nj][1] - mn0);
            const float p10 = __expf(sacc[nj][2] - mn1);
            const float p11 = __expf(sacc[nj][3] - mn1);
            s0 += p00 + p01;
            s1 += p10 + p11;
            sacc[nj][0] = __uint_as_float(f2tf(p00));
            sacc[nj][1] = __uint_as_float(f2tf(p01));
            sacc[nj][2] = __uint_as_float(f2tf(p10));
            sacc[nj][3] = __uint_as_float(f2tf(p11));
        }
        s0 += __shfl_xor_sync(0xffffffffu, s0, 1);
        s0 += __shfl_xor_sync(0xffffffffu, s0, 2);
        s1 += __shfl_xor_sync(0xffffffffu, s1, 1);
        s1 += __shfl_xor_sync(0xffffffffu, s1, 2);
        l0s = l0s*c0 + s0;  m0s = mn0;
        l1s = l1s*c1 + s1;  m1s = mn1;

        #pragma unroll
        for (int nj = 0; nj < 8; nj++) {
            o[nj][0] *= c0; o[nj][1] *= c0;
            o[nj][2] *= c1; o[nj][3] *= c1;
        }

        // O += P @ V  — P from registers (permuted key slots)
        #pragma unroll
        for (int nj = 0; nj < 8; nj++) {
            uint32_t pa[4] = { __float_as_uint(sacc[nj][0]),
                               __float_as_uint(sacc[nj][2]),
                               __float_as_uint(sacc[nj][1]),
                               __float_as_uint(sacc[nj][3]) };
            const uint32_t* v0 = (const uint32_t*)(Vs + (nj*8 + 2*tc)*VP);
            const uint32_t* v1 = v0 + VP;
            #pragma unroll
            for (int njo = 0; njo < 8; njo++) {
                uint32_t vb[2] = { v0[njo*8 + gr], v1[njo*8 + gr] };
                mma_tf32(o[njo], pa, vb);
            }
        }
    }

    // Normalize and write
    {
        const int row0 = wid*16 + gr;
        const float inv0 = 1.f / l0s;
        const float inv1 = 1.f / l1s;
        #pragma unroll
        for (int nj = 0; nj < 8; nj++) {
            const int col = nj*8 + 2*tc;
            *(float2*)(Og + (size_t)(m0 + row0)*HDD + col) =
                make_float2(o[nj][0]*inv0, o[nj][1]*inv0);
            *(float2*)(Og + (size_t)(m0 + row0 + 8)*HDD + col) =
                make_float2(o[nj][2]*inv1, o[nj][3]*inv1);
        }
    }
}

// ---------------------------------------------------------------------------
extern "C" void kernel_launch(void* const* d_in, const int* in_sizes, int n_in,
                              void* d_out, int out_size)
{
    const float* query = (const float*)d_in[0];
    const float* Wq = (const float*)d_in[1];
    const float* bq = (const float*)d_in[2];
    const float* Wk = (const float*)d_in[3];
    const float* bk = (const float*)d_in[4];
    const float* Wv = (const float*)d_in[5];
    const float* bv = (const float*)d_in[6];
    const float* Wo = (const float*)d_in[7];
    const float* bo = (const float*)d_in[8];
    const float* Wm1 = (const float*)d_in[9];
    const float* bm1 = (const float*)d_in[10];
    const float* Wm2 = (const float*)d_in[11];
    const float* bm2 = (const float*)d_in[12];
    const float* dop = (const float*)d_in[13];
    const float* ser = (const float*)d_in[14];
    const float* nor = (const float*)d_in[15];
    const float* ace = (const float*)d_in[16];
    const float* asc = (const float*)d_in[17];
    const float* abi = (const float*)d_in[18];
    float* out = (float*)d_out;

    float *q, *k, *v, *hid, *x;
    float *wq, *wk, *wv, *wo, *wm1, *wm2, *qr;
    cudaGetSymbolAddress((void**)&q,   g_q);
    cudaGetSymbolAddress((void**)&k,   g_k);
    cudaGetSymbolAddress((void**)&v,   g_v);
    cudaGetSymbolAddress((void**)&hid, g_hid);
    cudaGetSymbolAddress((void**)&x,   g_x);
    cudaGetSymbolAddress((void**)&wq,  g_wq);
    cudaGetSymbolAddress((void**)&wk,  g_wk);
    cudaGetSymbolAddress((void**)&wv,  g_wv);
    cudaGetSymbolAddress((void**)&wo,  g_wo);
    cudaGetSymbolAddress((void**)&wm1, g_wm1);
    cudaGetSymbolAddress((void**)&wm2, g_wm2);
    cudaGetSymbolAddress((void**)&qr,  g_qr);

    static int attrs_set = 0;
    if (!attrs_set) {
        cudaFuncSetAttribute(attn_mma_kernel,
            cudaFuncAttributeMaxDynamicSharedMemorySize, ATT_SMEM_BYTES);
        cudaFuncSetAttribute(gemm_mma_kernel,
            cudaFuncAttributeMaxDynamicSharedMemorySize, GEMM_SMEM_BYTES);
        attrs_set = 1;
    }

    const int M = BB * SS;          // 4096
    dim3 blk(256);

    // Prepass: round all GEMM operands to tf32 in one launch
    round_all_kernel<<<(SEG_TOT + 255)/256, 256>>>(
        Wq, Wk, Wv, Wo, Wm1, Wm2, query,
        wq, wk, wv, wo, wm1, wm2, qr);

    // Q, K, V projections (epilogue emits tf32 bits; Q pre-scaled by HD^-0.5)
    {
        dim3 grid(DD/128, M/128);
        gemm_mma_kernel<<<grid, blk, GEMM_SMEM_BYTES>>>(
            qr, wq, bq, q, M, DD, DD, 0, 1, 0.125f, 0,
            nullptr, nullptr, nullptr, nullptr, nullptr, nullptr);
        gemm_mma_kernel<<<grid, blk, GEMM_SMEM_BYTES>>>(
            qr, wk, bk, k, M, DD, DD, 0, 1, 1.0f, 0,
            nullptr, nullptr, nullptr, nullptr, nullptr, nullptr);
        gemm_mma_kernel<<<grid, blk, GEMM_SMEM_BYTES>>>(
            qr, wv, bv, v, M, DD, DD, 0, 1, 1.0f, 0,
            nullptr, nullptr, nullptr, nullptr, nullptr, nullptr);
    }

    // MLP1 overlaps nothing but is independent of attention; order: attention
    // must precede MLP2 (gate epilogue reads g_attn).
    {
        dim3 grid1(DM/128, M/128);
        gemm_mma_kernel<<<grid1, blk, GEMM_SMEM_BYTES>>>(
            qr, wm1, bm1, hid, M, DM, DD, 1, 0, 1.0f, 0,
            nullptr, nullptr, nullptr, nullptr, nullptr, nullptr);
    }

    // Attention
    {
        dim3 grid(SS/128, BB*HH);
        attn_mma_kernel<<<grid, blk, ATT_SMEM_BYTES>>>();
    }

    // MLP2 + fused gate/combine epilogue -> g_x (tf32 bits)
    {
        dim3 grid2(DD/128, M/128);
        gemm_mma_kernel<<<grid2, blk, GEMM_SMEM_BYTES>>>(
            hid, wm2, bm2, x, M, DD, DM, 0, 0, 0.f, 1,
            dop, ser, nor, ace, asc, abi);
    }

    // Output projection -> d_out (fp32 out)
    {
        dim3 grid(DD/128, M/128);
        gemm_mma_kernel<<<grid, blk, GEMM_SMEM_BYTES>>>(
            x, wo, bo, out, M, DD, DD, 0, 0, 0.f, 0,
            nullptr, nullptr, nullptr, nullptr, nullptr, nullptr);
    }
}